// round 8
// baseline (speedup 1.0000x reference)
#include <cuda_runtime.h>
#include <cuda_bf16.h>
#include <mma.h>

using namespace nvcuda;

// Problem dims
#define HID 1024
#define INP 1024
#define OUTD 512
#define BAT 64
#define SEQ 512
#define NG  4096   // 4 gates * HID

// ---------------------------------------------------------------------------
// Device scratch (static __device__ arrays — allocation-free per harness rules)
// ---------------------------------------------------------------------------
__device__ __nv_bfloat16 g_Xhi[(size_t)BAT * SEQ * INP];   // 67 MB
__device__ __nv_bfloat16 g_Xlo[(size_t)BAT * SEQ * INP];   // 67 MB
__device__ __nv_bfloat16 g_Wxhi[(size_t)NG * INP];         // 8 MB
__device__ __nv_bfloat16 g_Wxlo[(size_t)NG * INP];
__device__ __nv_bfloat16 g_Whhi[(size_t)NG * HID];
__device__ __nv_bfloat16 g_Whlo[(size_t)NG * HID];
__device__ float         g_P[(size_t)BAT * SEQ * NG];      // 512 MB (x-projection)
__device__ float         g_bias[NG];
__device__ float         g_c[BAT * HID];
__device__ float         g_h[BAT * HID];
__device__ __nv_bfloat16 g_hhi[BAT * HID];
__device__ __nv_bfloat16 g_hlo[BAT * HID];

// ---------------------------------------------------------------------------
// Prep: split fp32 -> (hi, lo) bf16 pair.  v ~= hi + lo with ~2^-17 residual.
// ---------------------------------------------------------------------------
__global__ void k_splitX(const float* __restrict__ X) {
    size_t n = (size_t)BAT * SEQ * INP;
    for (size_t i = (size_t)blockIdx.x * blockDim.x + threadIdx.x; i < n;
         i += (size_t)gridDim.x * blockDim.x) {
        float v = X[i];
        __nv_bfloat16 hv = __float2bfloat16(v);
        g_Xhi[i] = hv;
        g_Xlo[i] = __float2bfloat16(v - __bfloat162float(hv));
    }
}

// Gate-concatenated weight split: dst row n = g*HID + j holds src_g[j][k].
__global__ void k_splitWx(const float* __restrict__ w0, const float* __restrict__ w1,
                          const float* __restrict__ w2, const float* __restrict__ w3) {
    const float* src[4] = {w0, w1, w2, w3};
    size_t n = (size_t)NG * INP;
    for (size_t i = (size_t)blockIdx.x * blockDim.x + threadIdx.x; i < n;
         i += (size_t)gridDim.x * blockDim.x) {
        int    g   = (int)(i >> 20);            // HID*INP = 2^20 per gate
        size_t rem = i & ((size_t)(1u << 20) - 1);
        float v = src[g][rem];
        __nv_bfloat16 hv = __float2bfloat16(v);
        g_Wxhi[i] = hv;
        g_Wxlo[i] = __float2bfloat16(v - __bfloat162float(hv));
    }
}

__global__ void k_splitWh(const float* __restrict__ w0, const float* __restrict__ w1,
                          const float* __restrict__ w2, const float* __restrict__ w3) {
    const float* src[4] = {w0, w1, w2, w3};
    size_t n = (size_t)NG * HID;
    for (size_t i = (size_t)blockIdx.x * blockDim.x + threadIdx.x; i < n;
         i += (size_t)gridDim.x * blockDim.x) {
        int    g   = (int)(i >> 20);
        size_t rem = i & ((size_t)(1u << 20) - 1);
        float v = src[g][rem];
        __nv_bfloat16 hv = __float2bfloat16(v);
        g_Whhi[i] = hv;
        g_Whlo[i] = __float2bfloat16(v - __bfloat162float(hv));
    }
}

// Initial state + fused biases. Gate order: i, f, o, g.
__global__ void k_init(const float* __restrict__ c0, const float* __restrict__ h0,
                       const float* __restrict__ bhi_, const float* __restrict__ bxi_,
                       const float* __restrict__ bhf_, const float* __restrict__ bxf_,
                       const float* __restrict__ bho_, const float* __restrict__ bxo_,
                       const float* __restrict__ bhg_, const float* __restrict__ bxg_) {
    int idx = blockIdx.x * blockDim.x + threadIdx.x;
    if (idx < BAT * HID) {
        int j = idx & (HID - 1);
        g_c[idx] = c0[j];
        float hv = h0[j];
        g_h[idx] = hv;
        __nv_bfloat16 hh = __float2bfloat16(hv);
        g_hhi[idx] = hh;
        g_hlo[idx] = __float2bfloat16(hv - __bfloat162float(hh));
    }
    if (idx < NG) {
        int g = idx >> 10, j = idx & (HID - 1);
        const float* bh[4] = {bhi_, bhf_, bho_, bhg_};
        const float* bx[4] = {bxi_, bxf_, bxo_, bxg_};
        g_bias[idx] = bh[g][j] + bx[g][j];
    }
}

// ---------------------------------------------------------------------------
// X projection: P[m, n] = sum_k Xs[m,k] * Wxs[n,k]   (3-term split-bf16)
// m = b*SEQ + t (row-major X), n = gate*HID + j.
// CTA tile 64x64, 8 warps: warp = 16 rows x 32 cols, full K=1024.
// Grid: x = n-tile (fastest, so W stays hot in L2 and X streams DRAM once).
// ---------------------------------------------------------------------------
__global__ __launch_bounds__(256) void k_xproj() {
    const int    n0 = blockIdx.x * 64;
    const size_t m0 = (size_t)blockIdx.y * 64;
    const int w    = threadIdx.x >> 5;
    const int mrow = (w & 3) * 16;
    const int nc0  = (w >> 2) * 32;

    wmma::fragment<wmma::accumulator, 16, 16, 16, float> acc[2];
    wmma::fill_fragment(acc[0], 0.0f);
    wmma::fill_fragment(acc[1], 0.0f);
    wmma::fragment<wmma::matrix_a, 16, 16, 16, __nv_bfloat16, wmma::row_major> ahi, alo;
    wmma::fragment<wmma::matrix_b, 16, 16, 16, __nv_bfloat16, wmma::col_major> bhi, blo;

    const __nv_bfloat16* Ahi = g_Xhi + (m0 + mrow) * INP;
    const __nv_bfloat16* Alo = g_Xlo + (m0 + mrow) * INP;

    for (int k = 0; k < INP; k += 16) {
        wmma::load_matrix_sync(ahi, Ahi + k, INP);
        wmma::load_matrix_sync(alo, Alo + k, INP);
#pragma unroll
        for (int c = 0; c < 2; c++) {
            size_t boff = (size_t)(n0 + nc0 + c * 16) * INP + k;
            wmma::load_matrix_sync(bhi, g_Wxhi + boff, INP);
            wmma::load_matrix_sync(blo, g_Wxlo + boff, INP);
            wmma::mma_sync(acc[c], ahi, bhi, acc[c]);
            wmma::mma_sync(acc[c], ahi, blo, acc[c]);
            wmma::mma_sync(acc[c], alo, bhi, acc[c]);
        }
    }
#pragma unroll
    for (int c = 0; c < 2; c++)
        wmma::store_matrix_sync(g_P + (m0 + mrow) * NG + n0 + nc0 + c * 16,
                                acc[c], NG, wmma::mem_row_major);
}

// ---------------------------------------------------------------------------
// One recurrent timestep, fully fused: R = h @ Wh.T (split-bf16), gates,
// c/h update, h re-split.  64 CTAs, CTA owns hidden slice [j0, j0+16) for all
// 4 gates => tile M=64(batch) x N=64(4 gates x 16).  16 warps:
//   warp = (mrow: 4) x (nhalf: 2) x (ksec: 2 halves of K=1024).
// Partials reduced through 32 KB smem, then elementwise phase in-kernel.
// ---------------------------------------------------------------------------
__global__ __launch_bounds__(512) void k_step(int t) {
    __shared__ float part[2][64][64];

    const int j0    = blockIdx.x * 16;
    const int w     = threadIdx.x >> 5;
    const int mrow  = (w & 3) * 16;
    const int nhalf = (w >> 2) & 1;
    const int ksec  = w >> 3;

    wmma::fragment<wmma::accumulator, 16, 16, 16, float> acc[2];
    wmma::fill_fragment(acc[0], 0.0f);
    wmma::fill_fragment(acc[1], 0.0f);
    wmma::fragment<wmma::matrix_a, 16, 16, 16, __nv_bfloat16, wmma::row_major> ahi, alo;
    wmma::fragment<wmma::matrix_b, 16, 16, 16, __nv_bfloat16, wmma::col_major> bhi, blo;

    const __nv_bfloat16* Ahi = g_hhi + mrow * HID + ksec * 512;
    const __nv_bfloat16* Alo = g_hlo + mrow * HID + ksec * 512;

    for (int kk = 0; kk < 512; kk += 16) {
        wmma::load_matrix_sync(ahi, Ahi + kk, HID);
        wmma::load_matrix_sync(alo, Alo + kk, HID);
#pragma unroll
        for (int c = 0; c < 2; c++) {
            int gate = nhalf * 2 + c;
            size_t boff = (size_t)(gate * HID + j0) * HID + ksec * 512 + kk;
            wmma::load_matrix_sync(bhi, g_Whhi + boff, HID);
            wmma::load_matrix_sync(blo, g_Whlo + boff, HID);
            wmma::mma_sync(acc[c], ahi, bhi, acc[c]);
            wmma::mma_sync(acc[c], ahi, blo, acc[c]);
            wmma::mma_sync(acc[c], alo, bhi, acc[c]);
        }
    }
#pragma unroll
    for (int c = 0; c < 2; c++)
        wmma::store_matrix_sync(&part[ksec][mrow][nhalf * 32 + c * 16],
                                acc[c], 64, wmma::mem_row_major);
    __syncthreads();

    // Elementwise gate phase: 64 batches x 16 hidden per CTA.
    for (int idx = threadIdx.x; idx < BAT * 16; idx += blockDim.x) {
        int b = idx >> 4, jj = idx & 15;
        int j = j0 + jj;
        size_t pbase = ((size_t)b * SEQ + t) * NG + j;
        float pi = g_P[pbase          ] + g_bias[j          ] + part[0][b][jj     ] + part[1][b][jj     ];
        float pf = g_P[pbase +     HID] + g_bias[j +     HID] + part[0][b][16 + jj] + part[1][b][16 + jj];
        float po = g_P[pbase + 2 * HID] + g_bias[j + 2 * HID] + part[0][b][32 + jj] + part[1][b][32 + jj];
        float pg = g_P[pbase + 3 * HID] + g_bias[j + 3 * HID] + part[0][b][48 + jj] + part[1][b][48 + jj];

        float ig = 1.0f / (1.0f + expf(-pi));
        float fg = 1.0f / (1.0f + expf(-pf));
        float og = 1.0f / (1.0f + expf(-po));
        float gg = tanhf(pg);

        int hidx = b * HID + j;
        float cn = fg * g_c[hidx] + ig * gg;
        float hn = og * tanhf(cn);
        g_c[hidx] = cn;
        g_h[hidx] = hn;
        __nv_bfloat16 hh = __float2bfloat16(hn);
        g_hhi[hidx] = hh;
        g_hlo[hidx] = __float2bfloat16(hn - __bfloat162float(hh));
    }
}

// ---------------------------------------------------------------------------
// Final: out[b, o] = dot(h[b,:], w[o,:]).  One warp per output (coalesced).
// ---------------------------------------------------------------------------
__global__ void k_final(const float* __restrict__ w, float* __restrict__ out) {
    int gw   = (blockIdx.x * blockDim.x + threadIdx.x) >> 5;
    int lane = threadIdx.x & 31;
    if (gw >= BAT * OUTD) return;
    int b = gw >> 9, o = gw & (OUTD - 1);
    const float* hr = g_h + b * HID;
    const float* wr = w + (size_t)o * HID;
    float s = 0.0f;
    for (int k = lane; k < HID; k += 32) s = fmaf(hr[k], wr[k], s);
#pragma unroll
    for (int off = 16; off > 0; off >>= 1) s += __shfl_down_sync(0xFFFFFFFFu, s, off);
    if (lane == 0) out[b * OUTD + o] = s;
}

// ---------------------------------------------------------------------------
// Launch (graph-capturable: kernel launches only)
// ---------------------------------------------------------------------------
extern "C" void kernel_launch(void* const* d_in, const int* in_sizes, int n_in,
                              void* d_out, int out_size) {
    const float* X    = (const float*)d_in[0];
    const float* c0   = (const float*)d_in[1];
    const float* h0   = (const float*)d_in[2];
    const float* w_hi = (const float*)d_in[3];
    const float* w_xi = (const float*)d_in[4];
    const float* b_hi = (const float*)d_in[5];
    const float* b_xi = (const float*)d_in[6];
    const float* w_hf = (const float*)d_in[7];
    const float* w_xf = (const float*)d_in[8];
    const float* b_hf = (const float*)d_in[9];
    const float* b_xf = (const float*)d_in[10];
    const float* w_ho = (const float*)d_in[11];
    const float* w_xo = (const float*)d_in[12];
    const float* b_ho = (const float*)d_in[13];
    const float* b_xo = (const float*)d_in[14];
    const float* w_hg = (const float*)d_in[15];
    const float* w_xg = (const float*)d_in[16];
    const float* b_hg = (const float*)d_in[17];
    const float* b_xg = (const float*)d_in[18];
    const float* w    = (const float*)d_in[19];
    float* out = (float*)d_out;

    k_splitX<<<8192, 256>>>(X);
    k_splitWx<<<4096, 256>>>(w_xi, w_xf, w_xo, w_xg);
    k_splitWh<<<4096, 256>>>(w_hi, w_hf, w_ho, w_hg);
    k_init<<<(BAT * HID + 255) / 256, 256>>>(c0, h0, b_hi, b_xi, b_hf, b_xf,
                                             b_ho, b_xo, b_hg, b_xg);

    k_xproj<<<dim3(NG / 64, (BAT * SEQ) / 64), 256>>>();

    for (int t = 0; t < SEQ; t++) k_step<<<HID / 16, 512>>>(t);

    k_final<<<(BAT * OUTD * 32 + 255) / 256, 256>>>(w, out);
}

// round 9
// speedup vs baseline: 3.3392x; 3.3392x over previous
#include <cuda_runtime.h>
#include <cuda_bf16.h>
#include <mma.h>

using namespace nvcuda;

// Problem dims
#define HID 1024
#define INP 1024
#define OUTD 512
#define BAT 64
#define SEQ 512
#define NG  4096   // 4 gates * HID

#define NCTA 128   // persistent recurrence CTAs (<=148 SMs, 1/SM => all co-resident)
#define WLD  1040  // smem K-stride for weight rows (2080B = 65 banks, conflict-free)

// ---------------------------------------------------------------------------
// Device scratch (static __device__ arrays — allocation-free per harness rules)
// ---------------------------------------------------------------------------
__device__ __nv_bfloat16 g_Xhi[(size_t)BAT * SEQ * INP];
__device__ __nv_bfloat16 g_Xlo[(size_t)BAT * SEQ * INP];
__device__ __nv_bfloat16 g_Wxhi[(size_t)NG * INP];
__device__ __nv_bfloat16 g_Wxlo[(size_t)NG * INP];
__device__ __nv_bfloat16 g_Whhi[(size_t)NG * HID];
__device__ __nv_bfloat16 g_Whlo[(size_t)NG * HID];
__device__ float         g_P[(size_t)SEQ * BAT * NG];     // [t][b][4H] layout
__device__ float         g_bias[NG];
__device__ float         g_c[BAT * HID];
__device__ float         g_h[BAT * HID];
__device__ __nv_bfloat16 g_hbufhi[2][BAT * HID];          // double-buffered state
__device__ __nv_bfloat16 g_hbuflo[2][BAT * HID];
__device__ unsigned      g_barcnt;                        // grid barrier counter

// ---------------------------------------------------------------------------
// Prep: split fp32 -> (hi, lo) bf16 pair.  v ~= hi + lo with ~2^-17 residual.
// ---------------------------------------------------------------------------
__global__ void k_splitX(const float* __restrict__ X) {
    size_t n = (size_t)BAT * SEQ * INP;
    for (size_t i = (size_t)blockIdx.x * blockDim.x + threadIdx.x; i < n;
         i += (size_t)gridDim.x * blockDim.x) {
        float v = X[i];
        __nv_bfloat16 hv = __float2bfloat16(v);
        g_Xhi[i] = hv;
        g_Xlo[i] = __float2bfloat16(v - __bfloat162float(hv));
    }
}

__global__ void k_splitWx(const float* __restrict__ w0, const float* __restrict__ w1,
                          const float* __restrict__ w2, const float* __restrict__ w3) {
    const float* src[4] = {w0, w1, w2, w3};
    size_t n = (size_t)NG * INP;
    for (size_t i = (size_t)blockIdx.x * blockDim.x + threadIdx.x; i < n;
         i += (size_t)gridDim.x * blockDim.x) {
        int    g   = (int)(i >> 20);
        size_t rem = i & ((size_t)(1u << 20) - 1);
        float v = src[g][rem];
        __nv_bfloat16 hv = __float2bfloat16(v);
        g_Wxhi[i] = hv;
        g_Wxlo[i] = __float2bfloat16(v - __bfloat162float(hv));
    }
}

__global__ void k_splitWh(const float* __restrict__ w0, const float* __restrict__ w1,
                          const float* __restrict__ w2, const float* __restrict__ w3) {
    const float* src[4] = {w0, w1, w2, w3};
    size_t n = (size_t)NG * HID;
    for (size_t i = (size_t)blockIdx.x * blockDim.x + threadIdx.x; i < n;
         i += (size_t)gridDim.x * blockDim.x) {
        int    g   = (int)(i >> 20);
        size_t rem = i & ((size_t)(1u << 20) - 1);
        float v = src[g][rem];
        __nv_bfloat16 hv = __float2bfloat16(v);
        g_Whhi[i] = hv;
        g_Whlo[i] = __float2bfloat16(v - __bfloat162float(hv));
    }
}

// Initial state + fused biases + barrier reset. Gate order: i, f, o, g.
__global__ void k_init(const float* __restrict__ c0, const float* __restrict__ h0,
                       const float* __restrict__ bhi_, const float* __restrict__ bxi_,
                       const float* __restrict__ bhf_, const float* __restrict__ bxf_,
                       const float* __restrict__ bho_, const float* __restrict__ bxo_,
                       const float* __restrict__ bhg_, const float* __restrict__ bxg_) {
    int idx = blockIdx.x * blockDim.x + threadIdx.x;
    if (idx == 0) g_barcnt = 0u;
    if (idx < BAT * HID) {
        int j = idx & (HID - 1);
        g_c[idx] = c0[j];
        float hv = h0[j];
        g_h[idx] = hv;
        __nv_bfloat16 hh = __float2bfloat16(hv);
        g_hbufhi[0][idx] = hh;
        g_hbuflo[0][idx] = __float2bfloat16(hv - __bfloat162float(hh));
    }
    if (idx < NG) {
        int g = idx >> 10, j = idx & (HID - 1);
        const float* bh[4] = {bhi_, bhf_, bho_, bhg_};
        const float* bx[4] = {bxi_, bxf_, bxo_, bxg_};
        g_bias[idx] = bh[g][j] + bx[g][j];
    }
}

// ---------------------------------------------------------------------------
// X projection with smem staging: P[(t*BAT+b), n] = sum_k Xs[m,k]*Wxs[n,k]
// m = b*SEQ + t. CTA tile 64x64, K chunked by 64 through smem (ldm=72 pad).
// Grid x = n-tile (fastest) so W stays L2-hot while X streams DRAM once.
// ---------------------------------------------------------------------------
__global__ __launch_bounds__(256) void k_xproj() {
    __shared__ __nv_bfloat16 Ahi_s[64][72], Alo_s[64][72];
    __shared__ __nv_bfloat16 Bhi_s[64][72], Blo_s[64][72];

    const int n0  = blockIdx.x * 64;
    const int m0  = blockIdx.y * 64;
    const int tid = threadIdx.x;
    const int w    = tid >> 5;
    const int mrow = (w & 3) * 16;
    const int nc0  = (w >> 2) * 32;

    wmma::fragment<wmma::accumulator, 16, 16, 16, float> acc[2];
    wmma::fill_fragment(acc[0], 0.0f);
    wmma::fill_fragment(acc[1], 0.0f);
    wmma::fragment<wmma::matrix_a, 16, 16, 16, __nv_bfloat16, wmma::row_major> ahi, alo;
    wmma::fragment<wmma::matrix_b, 16, 16, 16, __nv_bfloat16, wmma::col_major> bhi, blo;

    for (int k0 = 0; k0 < INP; k0 += 64) {
        __syncthreads();
        // 64 rows x 8 uint4 (8 bf16 each) per array; 512 slots / 256 threads
        for (int s = tid; s < 512; s += 256) {
            int r = s >> 3, c8 = s & 7;
            size_t ga = (size_t)(m0 + r) * INP + k0 + c8 * 8;
            *(uint4*)&Ahi_s[r][c8 * 8] = *(const uint4*)&g_Xhi[ga];
            *(uint4*)&Alo_s[r][c8 * 8] = *(const uint4*)&g_Xlo[ga];
            size_t gb = (size_t)(n0 + r) * INP + k0 + c8 * 8;
            *(uint4*)&Bhi_s[r][c8 * 8] = *(const uint4*)&g_Wxhi[gb];
            *(uint4*)&Blo_s[r][c8 * 8] = *(const uint4*)&g_Wxlo[gb];
        }
        __syncthreads();
#pragma unroll
        for (int kk = 0; kk < 64; kk += 16) {
            wmma::load_matrix_sync(ahi, &Ahi_s[mrow][kk], 72);
            wmma::load_matrix_sync(alo, &Alo_s[mrow][kk], 72);
#pragma unroll
            for (int c = 0; c < 2; c++) {
                wmma::load_matrix_sync(bhi, &Bhi_s[nc0 + c * 16][kk], 72);
                wmma::load_matrix_sync(blo, &Blo_s[nc0 + c * 16][kk], 72);
                wmma::mma_sync(acc[c], ahi, bhi, acc[c]);
                wmma::mma_sync(acc[c], ahi, blo, acc[c]);
                wmma::mma_sync(acc[c], alo, bhi, acc[c]);
            }
        }
    }
    // store remapped to [t][b][n]: m = b*SEQ + t; tile rows are consecutive t
    int b  = m0 >> 9;             // m0 / SEQ
    int tb = (m0 & (SEQ - 1)) + mrow;
#pragma unroll
    for (int c = 0; c < 2; c++)
        wmma::store_matrix_sync(g_P + ((size_t)tb * BAT + b) * NG + n0 + nc0 + c * 16,
                                acc[c], BAT * NG, wmma::mem_row_major);
}

// ---------------------------------------------------------------------------
// Persistent recurrence: 128 CTAs, one launch, 512 steps internally.
// CTA owns hidden cols [j0, j0+8) for all 4 gates (N=32), M=64 batch, K=1024.
// Wh slice lives in smem (130 KB, loaded once). c lives in registers.
// Grid barrier: monotonic counter + release fence / acquire fence.
// 16 warps = (m-tile:4) x (K-section:4, 256 each); each warp does both n-tiles.
// ---------------------------------------------------------------------------
__global__ __launch_bounds__(512, 1) void k_rnn() {
    extern __shared__ char dynsm[];
    __nv_bfloat16* Whi = (__nv_bfloat16*)dynsm;            // [32][WLD]
    __nv_bfloat16* Wlo = Whi + 32 * WLD;                   // [32][WLD]
    float*         part = (float*)(Wlo + 32 * WLD);        // [4][64][32]

    const int tid = threadIdx.x;
    const int j0  = blockIdx.x * 8;
    const int w   = tid >> 5;
    const int mt  = w & 3;   // m tile: rows mt*16..
    const int ks  = w >> 2;  // K section: [ks*256, ks*256+256)

    // Load this CTA's weight slice into smem once. Row n = gate*8 + jj.
    for (int v = tid; v < 32 * 128; v += 512) {   // 128 uint4 per 1024-elem row
        int n = v >> 7, k8 = v & 127;
        int gate = n >> 3, jj = n & 7;
        size_t src = (size_t)(gate * HID + j0 + jj) * HID + k8 * 8;
        *(uint4*)(Whi + n * WLD + k8 * 8) = *(const uint4*)&g_Whhi[src];
        *(uint4*)(Wlo + n * WLD + k8 * 8) = *(const uint4*)&g_Whlo[src];
    }

    // Per-thread elementwise ownership: thread -> (b, jj), fixed for all steps.
    const int b  = tid >> 3;
    const int jj = tid & 7;
    const int j  = j0 + jj;
    float c_reg = g_c[b * HID + j];
    const float bias0 = g_bias[j];
    const float bias1 = g_bias[HID + j];
    const float bias2 = g_bias[2 * HID + j];
    const float bias3 = g_bias[3 * HID + j];

    __syncthreads();

    for (int t = 0; t < SEQ; t++) {
        const int rd = t & 1;

        // Prefetch this step's x-projection values (independent of h).
        size_t pb = ((size_t)t * BAT + b) * NG + j;
        float p0 = g_P[pb];
        float p1 = g_P[pb + HID];
        float p2 = g_P[pb + 2 * HID];
        float p3 = g_P[pb + 3 * HID];

        wmma::fragment<wmma::accumulator, 16, 16, 16, float> acc[2];
        wmma::fill_fragment(acc[0], 0.0f);
        wmma::fill_fragment(acc[1], 0.0f);
        wmma::fragment<wmma::matrix_a, 16, 16, 16, __nv_bfloat16, wmma::row_major> ahi, alo;
        wmma::fragment<wmma::matrix_b, 16, 16, 16, __nv_bfloat16, wmma::col_major> bhi, blo;

        const __nv_bfloat16* Ahi = g_hbufhi[rd] + mt * 16 * HID + ks * 256;
        const __nv_bfloat16* Alo = g_hbuflo[rd] + mt * 16 * HID + ks * 256;

#pragma unroll 4
        for (int kk = 0; kk < 256; kk += 16) {
            wmma::load_matrix_sync(ahi, Ahi + kk, HID);
            wmma::load_matrix_sync(alo, Alo + kk, HID);
#pragma unroll
            for (int nt = 0; nt < 2; nt++) {
                wmma::load_matrix_sync(bhi, Whi + (nt * 16) * WLD + ks * 256 + kk, WLD);
                wmma::load_matrix_sync(blo, Wlo + (nt * 16) * WLD + ks * 256 + kk, WLD);
                wmma::mma_sync(acc[nt], ahi, bhi, acc[nt]);
                wmma::mma_sync(acc[nt], ahi, blo, acc[nt]);
                wmma::mma_sync(acc[nt], alo, bhi, acc[nt]);
            }
        }
#pragma unroll
        for (int nt = 0; nt < 2; nt++)
            wmma::store_matrix_sync(&part[(ks * 64 + mt * 16) * 32 + nt * 16],
                                    acc[nt], 32, wmma::mem_row_major);
        __syncthreads();

        // Gates: sum K-section partials, add P + bias, update c (registers) & h.
        float si = p0 + bias0, sf = p1 + bias1, so = p2 + bias2, sg = p3 + bias3;
#pragma unroll
        for (int s = 0; s < 4; s++) {
            const float* pr = &part[(s * 64 + b) * 32];
            si += pr[jj];
            sf += pr[8 + jj];
            so += pr[16 + jj];
            sg += pr[24 + jj];
        }
        float ig = 1.0f / (1.0f + expf(-si));
        float fg = 1.0f / (1.0f + expf(-sf));
        float og = 1.0f / (1.0f + expf(-so));
        float gg = tanhf(sg);
        c_reg = fg * c_reg + ig * gg;
        float hn = og * tanhf(c_reg);

        int hidx = b * HID + j;
        g_h[hidx] = hn;                      // fp32 copy for the final GEMM
        __nv_bfloat16 hh = __float2bfloat16(hn);
        int wr = 1 - rd;
        g_hbufhi[wr][hidx] = hh;
        g_hbuflo[wr][hidx] = __float2bfloat16(hn - __bfloat162float(hh));

        // ---- grid barrier (release h(t), protect part smem reuse) ----
        __threadfence();                     // release: h writes -> L2, visible gpu-wide
        __syncthreads();
        if (tid == 0) {
            atomicAdd(&g_barcnt, 1u);
            unsigned tgt = (unsigned)(t + 1) * NCTA;
            while (((volatile unsigned*)&g_barcnt)[0] < tgt) __nanosleep(32);
        }
        __syncthreads();
        __threadfence();                     // acquire: invalidate stale L1 lines
    }
}

// ---------------------------------------------------------------------------
// Final: out[b, o] = dot(h[b,:], w[o,:]).  One warp per output (coalesced).
// ---------------------------------------------------------------------------
__global__ void k_final(const float* __restrict__ w, float* __restrict__ out) {
    int gw   = (blockIdx.x * blockDim.x + threadIdx.x) >> 5;
    int lane = threadIdx.x & 31;
    if (gw >= BAT * OUTD) return;
    int b = gw >> 9, o = gw & (OUTD - 1);
    const float* hr = g_h + b * HID;
    const float* wr = w + (size_t)o * HID;
    float s = 0.0f;
    for (int k = lane; k < HID; k += 32) s = fmaf(hr[k], wr[k], s);
#pragma unroll
    for (int off = 16; off > 0; off >>= 1) s += __shfl_down_sync(0xFFFFFFFFu, s, off);
    if (lane == 0) out[b * OUTD + o] = s;
}

// ---------------------------------------------------------------------------
// Launch (graph-capturable: kernel launches only; attribute set is immediate API)
// ---------------------------------------------------------------------------
extern "C" void kernel_launch(void* const* d_in, const int* in_sizes, int n_in,
                              void* d_out, int out_size) {
    const float* X    = (const float*)d_in[0];
    const float* c0   = (const float*)d_in[1];
    const float* h0   = (const float*)d_in[2];
    const float* w_hi = (const float*)d_in[3];
    const float* w_xi = (const float*)d_in[4];
    const float* b_hi = (const float*)d_in[5];
    const float* b_xi = (const float*)d_in[6];
    const float* w_hf = (const float*)d_in[7];
    const float* w_xf = (const float*)d_in[8];
    const float* b_hf = (const float*)d_in[9];
    const float* b_xf = (const float*)d_in[10];
    const float* w_ho = (const float*)d_in[11];
    const float* w_xo = (const float*)d_in[12];
    const float* b_ho = (const float*)d_in[13];
    const float* b_xo = (const float*)d_in[14];
    const float* w_hg = (const float*)d_in[15];
    const float* w_xg = (const float*)d_in[16];
    const float* b_hg = (const float*)d_in[17];
    const float* b_xg = (const float*)d_in[18];
    const float* w    = (const float*)d_in[19];
    float* out = (float*)d_out;

    const int RNN_SMEM = 2 * 32 * WLD * 2 + 4 * 64 * 32 * 4;   // 165,888 B
    cudaFuncSetAttribute(k_rnn, cudaFuncAttributeMaxDynamicSharedMemorySize, RNN_SMEM);

    k_splitX<<<8192, 256>>>(X);
    k_splitWx<<<4096, 256>>>(w_xi, w_xf, w_xo, w_xg);
    k_splitWh<<<4096, 256>>>(w_hi, w_hf, w_ho, w_hg);
    k_init<<<(BAT * HID + 255) / 256, 256>>>(c0, h0, b_hi, b_xi, b_hf, b_xf,
                                             b_ho, b_xo, b_hg, b_xg);

    k_xproj<<<dim3(NG / 64, (BAT * SEQ) / 64), 256>>>();

    k_rnn<<<NCTA, 512, RNN_SMEM>>>();

    k_final<<<(BAT * OUTD * 32 + 255) / 256, 256>>>(w, out);
}

// round 10
// speedup vs baseline: 4.2255x; 1.2654x over previous
#include <cuda_runtime.h>
#include <cuda_bf16.h>
#include <mma.h>
#include <cstdint>

using namespace nvcuda;

// Problem dims
#define HID 1024
#define INP 1024
#define OUTD 512
#define BAT 64
#define SEQ 512
#define NG  4096   // 4 gates * HID

#define NCTA 128   // persistent recurrence CTAs (1/SM, all co-resident)
#define ALD  1032  // smem A row stride in bf16 (2064B: conflict-free ldmatrix)
#define PLD  34    // partials row stride in floats (8B-aligned float2 stores)

// ---------------------------------------------------------------------------
// Device scratch (static __device__ arrays — allocation-free per harness rules)
// ---------------------------------------------------------------------------
__device__ __nv_bfloat16 g_Xhi[(size_t)BAT * SEQ * INP];
__device__ __nv_bfloat16 g_Xlo[(size_t)BAT * SEQ * INP];
__device__ __nv_bfloat16 g_Wxhi[(size_t)NG * INP];
__device__ __nv_bfloat16 g_Wxlo[(size_t)NG * INP];
__device__ __nv_bfloat16 g_Whhi[(size_t)NG * HID];
__device__ __nv_bfloat16 g_Whlo[(size_t)NG * HID];
__device__ float         g_P[(size_t)SEQ * BAT * NG];     // [t][b][4H]
__device__ float         g_bias[NG];
__device__ float         g_c[BAT * HID];
__device__ float         g_h[BAT * HID];
__device__ __nv_bfloat16 g_hbufhi[2][BAT * HID];          // double-buffered state
__device__ __nv_bfloat16 g_hbuflo[2][BAT * HID];
__device__ unsigned      g_barcnt;                        // grid barrier counter

// ---------------------------------------------------------------------------
// PTX helpers
// ---------------------------------------------------------------------------
__device__ __forceinline__ void mma16816(float* d, const uint32_t* a, const uint32_t* b) {
    asm volatile(
        "mma.sync.aligned.m16n8k16.row.col.f32.bf16.bf16.f32 "
        "{%0,%1,%2,%3}, {%4,%5,%6,%7}, {%8,%9}, {%0,%1,%2,%3};"
        : "+f"(d[0]), "+f"(d[1]), "+f"(d[2]), "+f"(d[3])
        : "r"(a[0]), "r"(a[1]), "r"(a[2]), "r"(a[3]), "r"(b[0]), "r"(b[1]));
}
__device__ __forceinline__ void ldmatrix_x4(uint32_t* r, uint32_t addr) {
    asm volatile("ldmatrix.sync.aligned.m8n8.x4.shared.b16 {%0,%1,%2,%3}, [%4];"
                 : "=r"(r[0]), "=r"(r[1]), "=r"(r[2]), "=r"(r[3]) : "r"(addr));
}
__device__ __forceinline__ void cp_async16(uint32_t dst, const void* src) {
    asm volatile("cp.async.cg.shared.global [%0], [%1], 16;" :: "r"(dst), "l"(src) : "memory");
}
__device__ __forceinline__ void cp_commit() { asm volatile("cp.async.commit_group;"); }
template <int N>
__device__ __forceinline__ void cp_wait() { asm volatile("cp.async.wait_group %0;" :: "n"(N)); }

// ---------------------------------------------------------------------------
// Prep: split fp32 -> (hi, lo) bf16 pair.
// ---------------------------------------------------------------------------
__global__ void k_splitX(const float* __restrict__ X) {
    size_t n = (size_t)BAT * SEQ * INP;
    for (size_t i = (size_t)blockIdx.x * blockDim.x + threadIdx.x; i < n;
         i += (size_t)gridDim.x * blockDim.x) {
        float v = X[i];
        __nv_bfloat16 hv = __float2bfloat16(v);
        g_Xhi[i] = hv;
        g_Xlo[i] = __float2bfloat16(v - __bfloat162float(hv));
    }
}

__global__ void k_splitWx(const float* __restrict__ w0, const float* __restrict__ w1,
                          const float* __restrict__ w2, const float* __restrict__ w3) {
    const float* src[4] = {w0, w1, w2, w3};
    size_t n = (size_t)NG * INP;
    for (size_t i = (size_t)blockIdx.x * blockDim.x + threadIdx.x; i < n;
         i += (size_t)gridDim.x * blockDim.x) {
        int    g   = (int)(i >> 20);
        size_t rem = i & ((size_t)(1u << 20) - 1);
        float v = src[g][rem];
        __nv_bfloat16 hv = __float2bfloat16(v);
        g_Wxhi[i] = hv;
        g_Wxlo[i] = __float2bfloat16(v - __bfloat162float(hv));
    }
}

__global__ void k_splitWh(const float* __restrict__ w0, const float* __restrict__ w1,
                          const float* __restrict__ w2, const float* __restrict__ w3) {
    const float* src[4] = {w0, w1, w2, w3};
    size_t n = (size_t)NG * HID;
    for (size_t i = (size_t)blockIdx.x * blockDim.x + threadIdx.x; i < n;
         i += (size_t)gridDim.x * blockDim.x) {
        int    g   = (int)(i >> 20);
        size_t rem = i & ((size_t)(1u << 20) - 1);
        float v = src[g][rem];
        __nv_bfloat16 hv = __float2bfloat16(v);
        g_Whhi[i] = hv;
        g_Whlo[i] = __float2bfloat16(v - __bfloat162float(hv));
    }
}

// Initial state + fused biases + barrier reset. Gate order: i, f, o, g.
__global__ void k_init(const float* __restrict__ c0, const float* __restrict__ h0,
                       const float* __restrict__ bhi_, const float* __restrict__ bxi_,
                       const float* __restrict__ bhf_, const float* __restrict__ bxf_,
                       const float* __restrict__ bho_, const float* __restrict__ bxo_,
                       const float* __restrict__ bhg_, const float* __restrict__ bxg_) {
    int idx = blockIdx.x * blockDim.x + threadIdx.x;
    if (idx == 0) g_barcnt = 0u;
    if (idx < BAT * HID) {
        int j = idx & (HID - 1);
        g_c[idx] = c0[j];
        float hv = h0[j];
        __nv_bfloat16 hh = __float2bfloat16(hv);
        g_hbufhi[0][idx] = hh;
        g_hbuflo[0][idx] = __float2bfloat16(hv - __bfloat162float(hh));
    }
    if (idx < NG) {
        int g = idx >> 10, j = idx & (HID - 1);
        const float* bh[4] = {bhi_, bhf_, bho_, bhg_};
        const float* bx[4] = {bxi_, bxf_, bxo_, bxg_};
        g_bias[idx] = bh[g][j] + bx[g][j];
    }
}

// ---------------------------------------------------------------------------
// X projection (unchanged wmma version): P[(t*BAT+b), n] = sum_k Xs[m,k]*Wxs[n,k]
// ---------------------------------------------------------------------------
__global__ __launch_bounds__(256) void k_xproj() {
    __shared__ __nv_bfloat16 Ahi_s[64][72], Alo_s[64][72];
    __shared__ __nv_bfloat16 Bhi_s[64][72], Blo_s[64][72];

    const int n0  = blockIdx.x * 64;
    const int m0  = blockIdx.y * 64;
    const int tid = threadIdx.x;
    const int w    = tid >> 5;
    const int mrow = (w & 3) * 16;
    const int nc0  = (w >> 2) * 32;

    wmma::fragment<wmma::accumulator, 16, 16, 16, float> acc[2];
    wmma::fill_fragment(acc[0], 0.0f);
    wmma::fill_fragment(acc[1], 0.0f);
    wmma::fragment<wmma::matrix_a, 16, 16, 16, __nv_bfloat16, wmma::row_major> ahi, alo;
    wmma::fragment<wmma::matrix_b, 16, 16, 16, __nv_bfloat16, wmma::col_major> bhi, blo;

    for (int k0 = 0; k0 < INP; k0 += 64) {
        __syncthreads();
        for (int s = tid; s < 512; s += 256) {
            int r = s >> 3, c8 = s & 7;
            size_t ga = (size_t)(m0 + r) * INP + k0 + c8 * 8;
            *(uint4*)&Ahi_s[r][c8 * 8] = *(const uint4*)&g_Xhi[ga];
            *(uint4*)&Alo_s[r][c8 * 8] = *(const uint4*)&g_Xlo[ga];
            size_t gb = (size_t)(n0 + r) * INP + k0 + c8 * 8;
            *(uint4*)&Bhi_s[r][c8 * 8] = *(const uint4*)&g_Wxhi[gb];
            *(uint4*)&Blo_s[r][c8 * 8] = *(const uint4*)&g_Wxlo[gb];
        }
        __syncthreads();
#pragma unroll
        for (int kk = 0; kk < 64; kk += 16) {
            wmma::load_matrix_sync(ahi, &Ahi_s[mrow][kk], 72);
            wmma::load_matrix_sync(alo, &Alo_s[mrow][kk], 72);
#pragma unroll
            for (int c = 0; c < 2; c++) {
                wmma::load_matrix_sync(bhi, &Bhi_s[nc0 + c * 16][kk], 72);
                wmma::load_matrix_sync(blo, &Blo_s[nc0 + c * 16][kk], 72);
                wmma::mma_sync(acc[c], ahi, bhi, acc[c]);
                wmma::mma_sync(acc[c], ahi, blo, acc[c]);
                wmma::mma_sync(acc[c], alo, bhi, acc[c]);
            }
        }
    }
    int b  = m0 >> 9;
    int tb = (m0 & (SEQ - 1)) + mrow;
#pragma unroll
    for (int c = 0; c < 2; c++)
        wmma::store_matrix_sync(g_P + ((size_t)tb * BAT + b) * NG + n0 + nc0 + c * 16,
                                acc[c], BAT * NG, wmma::mem_row_major);
}

// ---------------------------------------------------------------------------
// Persistent recurrence, mma.16816 + ldmatrix + weights-in-registers.
// CTA: hidden cols [j0, j0+8) x 4 gates (N=32), M=64 batch, K=1024.
// 16 warps = (nt: 4 gates) x (ks: 4 K-sections of 256). Warp tile n=8, its
// unique weight slice (8 x 256 x hi/lo) lives in 64 B32 registers, loaded once.
// h staged per 16-row mt-chunk via cp.async.cg (double-buffered, 64KB/chunk).
// ---------------------------------------------------------------------------
__global__ __launch_bounds__(512, 1) void k_rnn() {
    extern __shared__ char dynsm[];
    __nv_bfloat16* Ah = (__nv_bfloat16*)dynsm;            // [2][16][ALD]
    __nv_bfloat16* Al = Ah + 2 * 16 * ALD;                // [2][16][ALD]
    float*        part = (float*)(Al + 2 * 16 * ALD);     // [4][64][PLD]

    const int tid  = threadIdx.x;
    const int j0   = blockIdx.x * 8;
    const int wrp  = tid >> 5;
    const int lane = tid & 31;
    const int nt   = wrp & 3;   // gate
    const int ks   = wrp >> 2;  // K section [ks*256, +256)

    const uint32_t Ah_u = (uint32_t)__cvta_generic_to_shared(Ah);
    const uint32_t Al_u = (uint32_t)__cvta_generic_to_shared(Al);

    // ---- load this warp's weight fragments into registers (once) ----
    // B col-major fragment: thread holds W[n = nt*H + j0 + lane/4][k, k+1] and [k+8, k+9]
    const int n_lane = lane >> 2;
    const int k_lane = (lane & 3) * 2;
    const size_t wrow = (size_t)(nt * HID + j0 + n_lane) * HID + ks * 256 + k_lane;
    uint32_t bh[16][2], bl[16][2];
#pragma unroll
    for (int kk = 0; kk < 16; kk++) {
        bh[kk][0] = *(const uint32_t*)&g_Whhi[wrow + kk * 16];
        bh[kk][1] = *(const uint32_t*)&g_Whhi[wrow + kk * 16 + 8];
        bl[kk][0] = *(const uint32_t*)&g_Whlo[wrow + kk * 16];
        bl[kk][1] = *(const uint32_t*)&g_Whlo[wrow + kk * 16 + 8];
    }

    // ldmatrix lane offset within a staged chunk (elements)
    const uint32_t a_lane_off = (uint32_t)((lane & 15) * ALD + (lane >> 4) * 8);

    // Per-thread elementwise ownership (b, jj)
    const int b  = tid >> 3;
    const int jj = tid & 7;
    const int j  = j0 + jj;
    float c_reg = g_c[b * HID + j];
    const float bias0 = g_bias[j];
    const float bias1 = g_bias[HID + j];
    const float bias2 = g_bias[2 * HID + j];
    const float bias3 = g_bias[3 * HID + j];

    __syncthreads();

    for (int t = 0; t < SEQ; t++) {
        const int rd = t & 1;
        const __nv_bfloat16* hbh = g_hbufhi[rd];
        const __nv_bfloat16* hbl = g_hbuflo[rd];

        // Prefetch x-projection for this thread's elements
        size_t pb = ((size_t)t * BAT + b) * NG + j;
        float p0 = g_P[pb];
        float p1 = g_P[pb + HID];
        float p2 = g_P[pb + 2 * HID];
        float p3 = g_P[pb + 3 * HID];

        float acc[4][4];
#pragma unroll
        for (int m = 0; m < 4; m++)
#pragma unroll
            for (int q = 0; q < 4; q++) acc[m][q] = 0.0f;

        // ---- stage chunk 0 ----
        {
#pragma unroll
            for (int q = 0; q < 8; q++) {
                int idx = q * 512 + tid;
                int half = idx >> 11, rr = (idx >> 7) & 15, c = idx & 127;
                const __nv_bfloat16* src =
                    (half ? hbl : hbh) + (size_t)rr * HID + c * 8;   // mt=0
                uint32_t dst = (half ? Al_u : Ah_u) + (uint32_t)(rr * ALD + c * 8) * 2;
                cp_async16(dst, src);
            }
            cp_commit();
        }

        for (int mt = 0; mt < 4; mt++) {
            const int buf = mt & 1;
            if (mt < 3) {   // stage next chunk into the other buffer
                const int nb = 1 - buf;
#pragma unroll
                for (int q = 0; q < 8; q++) {
                    int idx = q * 512 + tid;
                    int half = idx >> 11, rr = (idx >> 7) & 15, c = idx & 127;
                    const __nv_bfloat16* src =
                        (half ? hbl : hbh) + (size_t)((mt + 1) * 16 + rr) * HID + c * 8;
                    uint32_t dst = (half ? Al_u : Ah_u) +
                                   (uint32_t)((nb * 16 + rr) * ALD + c * 8) * 2;
                    cp_async16(dst, src);
                }
                cp_commit();
                cp_wait<1>();
            } else {
                cp_wait<0>();
            }
            __syncthreads();

            // compute this chunk: warp K-section ks, 16 k-steps
            const uint32_t ahb = Ah_u + (uint32_t)(buf * 16 * ALD + a_lane_off + ks * 256) * 2;
            const uint32_t alb = Al_u + (uint32_t)(buf * 16 * ALD + a_lane_off + ks * 256) * 2;
#pragma unroll
            for (int kk = 0; kk < 16; kk++) {
                uint32_t ah[4], al[4];
                ldmatrix_x4(ah, ahb + kk * 32);
                ldmatrix_x4(al, alb + kk * 32);
                mma16816(acc[mt], ah, bh[kk]);   // hi*hi
                mma16816(acc[mt], ah, bl[kk]);   // hi*lo
                mma16816(acc[mt], al, bh[kk]);   // lo*hi
            }
            __syncthreads();   // before next stage overwrites buf
        }

        // ---- store partials: part[ks][mt*16 + row][nt*8 + col] ----
        {
            const int row = lane >> 2;
            const int col = nt * 8 + (lane & 3) * 2;
#pragma unroll
            for (int m = 0; m < 4; m++) {
                float* p0p = &part[(ks * 64 + m * 16 + row) * PLD + col];
                *(float2*)p0p = make_float2(acc[m][0], acc[m][1]);
                float* p1p = &part[(ks * 64 + m * 16 + row + 8) * PLD + col];
                *(float2*)p1p = make_float2(acc[m][2], acc[m][3]);
            }
        }
        __syncthreads();

        // ---- gates: sum 4 K-section partials + P + bias ----
        float si = p0 + bias0, sf = p1 + bias1, so = p2 + bias2, sg = p3 + bias3;
#pragma unroll
        for (int s = 0; s < 4; s++) {
            const float* pr = &part[(s * 64 + b) * PLD];
            si += pr[jj];
            sf += pr[8 + jj];
            so += pr[16 + jj];
            sg += pr[24 + jj];
        }
        float ig = 1.0f / (1.0f + expf(-si));
        float fg = 1.0f / (1.0f + expf(-sf));
        float og = 1.0f / (1.0f + expf(-so));
        float gg = tanhf(sg);
        c_reg = fg * c_reg + ig * gg;
        float hn = og * tanhf(c_reg);

        int hidx = b * HID + j;
        if (t == SEQ - 1) g_h[hidx] = hn;          // fp32 h for final GEMM
        __nv_bfloat16 hh = __float2bfloat16(hn);
        int wr = 1 - rd;
        g_hbufhi[wr][hidx] = hh;
        g_hbuflo[wr][hidx] = __float2bfloat16(hn - __bfloat162float(hh));

        // ---- grid barrier (release h(t); protect smem reuse) ----
        __threadfence();
        __syncthreads();
        if (tid == 0) {
            atomicAdd(&g_barcnt, 1u);
            unsigned tgt = (unsigned)(t + 1) * NCTA;
            while (((volatile unsigned*)&g_barcnt)[0] < tgt) __nanosleep(32);
        }
        __syncthreads();
        __threadfence();
    }
}

// ---------------------------------------------------------------------------
// Final: out[b, o] = dot(h[b,:], w[o,:]).  One warp per output.
// ---------------------------------------------------------------------------
__global__ void k_final(const float* __restrict__ w, float* __restrict__ out) {
    int gw   = (blockIdx.x * blockDim.x + threadIdx.x) >> 5;
    int lane = threadIdx.x & 31;
    if (gw >= BAT * OUTD) return;
    int b = gw >> 9, o = gw & (OUTD - 1);
    const float* hr = g_h + b * HID;
    const float* wr = w + (size_t)o * HID;
    float s = 0.0f;
    for (int k = lane; k < HID; k += 32) s = fmaf(hr[k], wr[k], s);
#pragma unroll
    for (int off = 16; off > 0; off >>= 1) s += __shfl_down_sync(0xFFFFFFFFu, s, off);
    if (lane == 0) out[b * OUTD + o] = s;
}

// ---------------------------------------------------------------------------
// Launch (graph-capturable)
// ---------------------------------------------------------------------------
extern "C" void kernel_launch(void* const* d_in, const int* in_sizes, int n_in,
                              void* d_out, int out_size) {
    const float* X    = (const float*)d_in[0];
    const float* c0   = (const float*)d_in[1];
    const float* h0   = (const float*)d_in[2];
    const float* w_hi = (const float*)d_in[3];
    const float* w_xi = (const float*)d_in[4];
    const float* b_hi = (const float*)d_in[5];
    const float* b_xi = (const float*)d_in[6];
    const float* w_hf = (const float*)d_in[7];
    const float* w_xf = (const float*)d_in[8];
    const float* b_hf = (const float*)d_in[9];
    const float* b_xf = (const float*)d_in[10];
    const float* w_ho = (const float*)d_in[11];
    const float* w_xo = (const float*)d_in[12];
    const float* b_ho = (const float*)d_in[13];
    const float* b_xo = (const float*)d_in[14];
    const float* w_hg = (const float*)d_in[15];
    const float* w_xg = (const float*)d_in[16];
    const float* b_hg = (const float*)d_in[17];
    const float* b_xg = (const float*)d_in[18];
    const float* w    = (const float*)d_in[19];
    float* out = (float*)d_out;

    const int RNN_SMEM = 2 * 2 * 16 * ALD * 2 + 4 * 64 * PLD * 4;  // 166,912 B
    cudaFuncSetAttribute(k_rnn, cudaFuncAttributeMaxDynamicSharedMemorySize, RNN_SMEM);

    k_splitX<<<8192, 256>>>(X);
    k_splitWx<<<4096, 256>>>(w_xi, w_xf, w_xo, w_xg);
    k_splitWh<<<4096, 256>>>(w_hi, w_hf, w_ho, w_hg);
    k_init<<<(BAT * HID + 255) / 256, 256>>>(c0, h0, b_hi, b_xi, b_hf, b_xf,
                                             b_ho, b_xo, b_hg, b_xg);

    k_xproj<<<dim3(NG / 64, (BAT * SEQ) / 64), 256>>>();

    k_rnn<<<NCTA, 512, RNN_SMEM>>>();

    k_final<<<(BAT * OUTD * 32 + 255) / 256, 256>>>(w, out);
}

// round 13
// speedup vs baseline: 4.7897x; 1.1335x over previous
#include <cuda_runtime.h>
#include <cuda_bf16.h>
#include <cstdint>

// Problem dims
#define HID 1024
#define INP 1024
#define OUTD 512
#define BAT 64
#define SEQ 512
#define NG  4096   // 4 gates * HID

#define NCTA 128   // persistent recurrence CTAs (1/SM, all co-resident)
#define ALD  1032  // rnn smem A row stride in bf16 (conflict-free ldmatrix)
#define PLD  34    // rnn partials row stride in floats

// ---------------------------------------------------------------------------
// Device scratch
// ---------------------------------------------------------------------------
__device__ __nv_bfloat16 g_Xhi[(size_t)BAT * SEQ * INP];
__device__ __nv_bfloat16 g_Xlo[(size_t)BAT * SEQ * INP];
__device__ __nv_bfloat16 g_Wxhi[(size_t)NG * INP];
__device__ __nv_bfloat16 g_Wxlo[(size_t)NG * INP];
__device__ __nv_bfloat16 g_Whhi[(size_t)NG * HID];
__device__ __nv_bfloat16 g_Whlo[(size_t)NG * HID];
__device__ float         g_P[(size_t)SEQ * BAT * NG];     // [t][b][4H]
__device__ float         g_bias[NG];
__device__ float         g_c[BAT * HID];
__device__ float         g_h[BAT * HID];
__device__ __nv_bfloat16 g_hbufhi[2][BAT * HID];
__device__ __nv_bfloat16 g_hbuflo[2][BAT * HID];
__device__ unsigned      g_flag[NCTA * 32];               // barrier flags, 128B strided

// ---------------------------------------------------------------------------
// PTX helpers
// ---------------------------------------------------------------------------
__device__ __forceinline__ void mma16816(float* d, const uint32_t* a, const uint32_t* b) {
    asm volatile(
        "mma.sync.aligned.m16n8k16.row.col.f32.bf16.bf16.f32 "
        "{%0,%1,%2,%3}, {%4,%5,%6,%7}, {%8,%9}, {%0,%1,%2,%3};"
        : "+f"(d[0]), "+f"(d[1]), "+f"(d[2]), "+f"(d[3])
        : "r"(a[0]), "r"(a[1]), "r"(a[2]), "r"(a[3]), "r"(b[0]), "r"(b[1]));
}
__device__ __forceinline__ void ldmatrix_x4(uint32_t* r, uint32_t addr) {
    asm volatile("ldmatrix.sync.aligned.m8n8.x4.shared.b16 {%0,%1,%2,%3}, [%4];"
                 : "=r"(r[0]), "=r"(r[1]), "=r"(r[2]), "=r"(r[3]) : "r"(addr));
}
__device__ __forceinline__ void cp_async16(uint32_t dst, const void* src) {
    asm volatile("cp.async.cg.shared.global [%0], [%1], 16;" :: "r"(dst), "l"(src) : "memory");
}
__device__ __forceinline__ void cp_commit() { asm volatile("cp.async.commit_group;"); }
template <int N>
__device__ __forceinline__ void cp_wait() { asm volatile("cp.async.wait_group %0;" :: "n"(N)); }

// ---------------------------------------------------------------------------
// Prep kernels
// ---------------------------------------------------------------------------
__global__ void k_splitX(const float* __restrict__ X) {
    size_t n = (size_t)BAT * SEQ * INP;
    for (size_t i = (size_t)blockIdx.x * blockDim.x + threadIdx.x; i < n;
         i += (size_t)gridDim.x * blockDim.x) {
        float v = X[i];
        __nv_bfloat16 hv = __float2bfloat16(v);
        g_Xhi[i] = hv;
        g_Xlo[i] = __float2bfloat16(v - __bfloat162float(hv));
    }
}

__global__ void k_splitWx(const float* __restrict__ w0, const float* __restrict__ w1,
                          const float* __restrict__ w2, const float* __restrict__ w3) {
    const float* src[4] = {w0, w1, w2, w3};
    size_t n = (size_t)NG * INP;
    for (size_t i = (size_t)blockIdx.x * blockDim.x + threadIdx.x; i < n;
         i += (size_t)gridDim.x * blockDim.x) {
        int    g   = (int)(i >> 20);
        size_t rem = i & ((size_t)(1u << 20) - 1);
        float v = src[g][rem];
        __nv_bfloat16 hv = __float2bfloat16(v);
        g_Wxhi[i] = hv;
        g_Wxlo[i] = __float2bfloat16(v - __bfloat162float(hv));
    }
}

__global__ void k_splitWh(const float* __restrict__ w0, const float* __restrict__ w1,
                          const float* __restrict__ w2, const float* __restrict__ w3) {
    const float* src[4] = {w0, w1, w2, w3};
    size_t n = (size_t)NG * HID;
    for (size_t i = (size_t)blockIdx.x * blockDim.x + threadIdx.x; i < n;
         i += (size_t)gridDim.x * blockDim.x) {
        int    g   = (int)(i >> 20);
        size_t rem = i & ((size_t)(1u << 20) - 1);
        float v = src[g][rem];
        __nv_bfloat16 hv = __float2bfloat16(v);
        g_Whhi[i] = hv;
        g_Whlo[i] = __float2bfloat16(v - __bfloat162float(hv));
    }
}

__global__ void k_init(const float* __restrict__ c0, const float* __restrict__ h0,
                       const float* __restrict__ bhi_, const float* __restrict__ bxi_,
                       const float* __restrict__ bhf_, const float* __restrict__ bxf_,
                       const float* __restrict__ bho_, const float* __restrict__ bxo_,
                       const float* __restrict__ bhg_, const float* __restrict__ bxg_) {
    int idx = blockIdx.x * blockDim.x + threadIdx.x;
    if (idx < NCTA * 32) g_flag[idx] = 0u;
    if (idx < BAT * HID) {
        int j = idx & (HID - 1);
        g_c[idx] = c0[j];
        float hv = h0[j];
        __nv_bfloat16 hh = __float2bfloat16(hv);
        g_hbufhi[0][idx] = hh;
        g_hbuflo[0][idx] = __float2bfloat16(hv - __bfloat162float(hh));
    }
    if (idx < NG) {
        int g = idx >> 10, j = idx & (HID - 1);
        const float* bh[4] = {bhi_, bhf_, bho_, bhg_};
        const float* bx[4] = {bxi_, bxf_, bxo_, bxg_};
        g_bias[idx] = bh[g][j] + bx[g][j];
    }
}

// ---------------------------------------------------------------------------
// X projection v3: mma.16816 + ldmatrix + cp.async double-buffered pipeline.
// CTA tile M=128 x N=64, 8 warps = (mwarp:4) x (nwarp:2), warp tile 32x32.
// K chunked by 64, smem rows padded to 72 bf16 (144B) => conflict-free.
// 3-term split-bf16: hi*hi + hi*lo + lo*hi.
// ---------------------------------------------------------------------------
#define XLD 72
// byte offsets inside one smem buffer
#define XO_AH 0
#define XO_AL 18432
#define XO_BH 36864
#define XO_BL 46080
#define XBUF  55296
#define XP_SMEM (2 * XBUF)   // 110,592 B

__global__ __launch_bounds__(256) void k_xproj3() {
    extern __shared__ char smem[];
    const uint32_t sb = (uint32_t)__cvta_generic_to_shared(smem);

    const int tid   = threadIdx.x;
    const int wid   = tid >> 5;
    const int lane  = tid & 31;
    const int mwarp = wid & 3;     // 32-row slice
    const int nwarp = wid >> 2;    // 32-col slice
    const int n0    = blockIdx.x * 64;
    const int m0    = blockIdx.y * 128;

    float acc[2][4][4];
#pragma unroll
    for (int mt = 0; mt < 2; mt++)
#pragma unroll
        for (int nt = 0; nt < 4; nt++)
#pragma unroll
            for (int q = 0; q < 4; q++) acc[mt][nt][q] = 0.0f;

    // ldmatrix lane address components
    const uint32_t a_off = (uint32_t)((lane & 15) * (XLD * 2) + (lane >> 4) * 16);
    const int bmat = lane >> 3;          // 0..3
    const int brow = lane & 7;
    const uint32_t b_off = (uint32_t)(((bmat >> 1) * 8 + brow) * (XLD * 2) + (bmat & 1) * 16);

    // ---- fill helper (chunk k0 -> buffer bb) ----
    auto fill = [&](int k0, uint32_t bb) {
#pragma unroll
        for (int q = 0; q < 12; q++) {
            int idx = q * 256 + tid;          // 0..3071
            if (idx < 2048) {                 // A: hi then lo
                int half = idx >> 10, row = (idx >> 3) & 127, c = idx & 7;
                const __nv_bfloat16* src =
                    (half ? g_Xlo : g_Xhi) + (size_t)(m0 + row) * INP + k0 + c * 8;
                cp_async16(bb + (half ? XO_AL : XO_AH) + (uint32_t)(row * XLD + c * 8) * 2, src);
            } else {                          // B: hi then lo
                int r2 = idx - 2048;
                int half = r2 >> 9, row = (r2 >> 3) & 63, c = r2 & 7;
                const __nv_bfloat16* src =
                    (half ? g_Wxlo : g_Wxhi) + (size_t)(n0 + row) * INP + k0 + c * 8;
                cp_async16(bb + (half ? XO_BL : XO_BH) + (uint32_t)(row * XLD + c * 8) * 2, src);
            }
        }
        cp_commit();
    };

    fill(0, sb);                               // chunk 0 -> buf 0
    for (int ch = 0; ch < 16; ch++) {
        const uint32_t bb = sb + (ch & 1) * XBUF;
        if (ch < 15) {
            fill((ch + 1) * 64, sb + ((ch + 1) & 1) * XBUF);
            cp_wait<1>();
        } else {
            cp_wait<0>();
        }
        __syncthreads();

#pragma unroll
        for (int kk = 0; kk < 4; kk++) {       // 4 k16-steps per 64-chunk
            uint32_t ah[2][4], al[2][4];
#pragma unroll
            for (int mt = 0; mt < 2; mt++) {
                uint32_t base = (uint32_t)((mwarp * 32 + mt * 16) * (XLD * 2) + kk * 32);
                ldmatrix_x4(ah[mt], bb + XO_AH + base + a_off);
                ldmatrix_x4(al[mt], bb + XO_AL + base + a_off);
            }
            uint32_t bh[8], bl[8];
#pragma unroll
            for (int g = 0; g < 2; g++) {      // two n16 groups
                uint32_t base = (uint32_t)((nwarp * 32 + g * 16) * (XLD * 2) + kk * 32);
                ldmatrix_x4(bh + g * 4, bb + XO_BH + base + b_off);
                ldmatrix_x4(bl + g * 4, bb + XO_BL + base + b_off);
            }
#pragma unroll
            for (int mt = 0; mt < 2; mt++)
#pragma unroll
                for (int nt = 0; nt < 4; nt++) {
                    mma16816(acc[mt][nt], ah[mt], bh + nt * 2);
                    mma16816(acc[mt][nt], ah[mt], bl + nt * 2);
                    mma16816(acc[mt][nt], al[mt], bh + nt * 2);
                }
        }
        __syncthreads();
    }

    // Epilogue: store to g_P in [t][b][n] layout (m = b*SEQ + t)
#pragma unroll
    for (int mt = 0; mt < 2; mt++) {
        int mrow0 = m0 + mwarp * 32 + mt * 16 + (lane >> 2);
#pragma unroll
        for (int half = 0; half < 2; half++) {
            int m = mrow0 + half * 8;
            int b = m >> 9, t = m & (SEQ - 1);
            float* dst = g_P + ((size_t)t * BAT + b) * NG + n0 + nwarp * 32 + (lane & 3) * 2;
#pragma unroll
            for (int nt = 0; nt < 4; nt++)
                *(float2*)(dst + nt * 8) =
                    make_float2(acc[mt][nt][half * 2], acc[mt][nt][half * 2 + 1]);
        }
    }
}

// ---------------------------------------------------------------------------
// Persistent recurrence: mma.16816, weights-in-registers, 3 independent
// accumulator chains per warp, distributed-flag grid barrier.
// CTA: hidden cols [j0, j0+8) x 4 gates (N=32), M=64 batch, K=1024.
// 16 warps = (nt: 4 gates) x (ks: 4 K-sections of 256).
// ---------------------------------------------------------------------------
__global__ __launch_bounds__(512, 1) void k_rnn() {
    extern __shared__ char dynsm[];
    __nv_bfloat16* Ah = (__nv_bfloat16*)dynsm;            // [2][16][ALD]
    __nv_bfloat16* Al = Ah + 2 * 16 * ALD;                // [2][16][ALD]
    float*        part = (float*)(Al + 2 * 16 * ALD);     // [4][64][PLD]

    const int tid  = threadIdx.x;
    const int j0   = blockIdx.x * 8;
    const int wrp  = tid >> 5;
    const int lane = tid & 31;
    const int nt   = wrp & 3;   // gate
    const int ks   = wrp >> 2;  // K section [ks*256, +256)

    const uint32_t Ah_u = (uint32_t)__cvta_generic_to_shared(Ah);
    const uint32_t Al_u = (uint32_t)__cvta_generic_to_shared(Al);

    // Warp-unique weight fragments in registers (loaded once)
    const int n_lane = lane >> 2;
    const int k_lane = (lane & 3) * 2;
    const size_t wrow = (size_t)(nt * HID + j0 + n_lane) * HID + ks * 256 + k_lane;
    uint32_t bh[16][2], bl[16][2];
#pragma unroll
    for (int kk = 0; kk < 16; kk++) {
        bh[kk][0] = *(const uint32_t*)&g_Whhi[wrow + kk * 16];
        bh[kk][1] = *(const uint32_t*)&g_Whhi[wrow + kk * 16 + 8];
        bl[kk][0] = *(const uint32_t*)&g_Whlo[wrow + kk * 16];
        bl[kk][1] = *(const uint32_t*)&g_Whlo[wrow + kk * 16 + 8];
    }

    const uint32_t a_lane_off = (uint32_t)((lane & 15) * ALD + (lane >> 4) * 8);

    const int b  = tid >> 3;
    const int jj = tid & 7;
    const int j  = j0 + jj;
    float c_reg = g_c[b * HID + j];
    const float bias0 = g_bias[j];
    const float bias1 = g_bias[HID + j];
    const float bias2 = g_bias[2 * HID + j];
    const float bias3 = g_bias[3 * HID + j];

    __syncthreads();

    for (int t = 0; t < SEQ; t++) {
        const int rd = t & 1;
        const __nv_bfloat16* hbh = g_hbufhi[rd];
        const __nv_bfloat16* hbl = g_hbuflo[rd];

        size_t pb = ((size_t)t * BAT + b) * NG + j;
        float p0 = g_P[pb];
        float p1 = g_P[pb + HID];
        float p2 = g_P[pb + 2 * HID];
        float p3 = g_P[pb + 3 * HID];

        // ---- stage chunk 0 ----
        {
#pragma unroll
            for (int q = 0; q < 8; q++) {
                int idx = q * 512 + tid;
                int half = idx >> 11, rr = (idx >> 7) & 15, c = idx & 127;
                const __nv_bfloat16* src =
                    (half ? hbl : hbh) + (size_t)rr * HID + c * 8;
                uint32_t dst = (half ? Al_u : Ah_u) + (uint32_t)(rr * ALD + c * 8) * 2;
                cp_async16(dst, src);
            }
            cp_commit();
        }

        const int prow = lane >> 2;
        const int pcol = nt * 8 + (lane & 3) * 2;

        for (int mt = 0; mt < 4; mt++) {
            const int buf = mt & 1;
            if (mt < 3) {
                const int nb = 1 - buf;
#pragma unroll
                for (int q = 0; q < 8; q++) {
                    int idx = q * 512 + tid;
                    int half = idx >> 11, rr = (idx >> 7) & 15, c = idx & 127;
                    const __nv_bfloat16* src =
                        (half ? hbl : hbh) + (size_t)((mt + 1) * 16 + rr) * HID + c * 8;
                    uint32_t dst = (half ? Al_u : Ah_u) +
                                   (uint32_t)((nb * 16 + rr) * ALD + c * 8) * 2;
                    cp_async16(dst, src);
                }
                cp_commit();
                cp_wait<1>();
            } else {
                cp_wait<0>();
            }
            __syncthreads();

            // 3 independent accumulator chains (one per split term)
            float aA[4] = {0.f, 0.f, 0.f, 0.f};
            float aB[4] = {0.f, 0.f, 0.f, 0.f};
            float aC[4] = {0.f, 0.f, 0.f, 0.f};
            const uint32_t ahb = Ah_u + (uint32_t)(buf * 16 * ALD + a_lane_off + ks * 256) * 2;
            const uint32_t alb = Al_u + (uint32_t)(buf * 16 * ALD + a_lane_off + ks * 256) * 2;
#pragma unroll
            for (int kk = 0; kk < 16; kk++) {
                uint32_t ah[4], al[4];
                ldmatrix_x4(ah, ahb + kk * 32);
                ldmatrix_x4(al, alb + kk * 32);
                mma16816(aA, ah, bh[kk]);   // hi*hi
                mma16816(aB, ah, bl[kk]);   // hi*lo
                mma16816(aC, al, bh[kk]);   // lo*hi
            }
            {
                float* q0 = &part[(ks * 64 + mt * 16 + prow) * PLD + pcol];
                *(float2*)q0 = make_float2(aA[0] + aB[0] + aC[0], aA[1] + aB[1] + aC[1]);
                float* q1 = &part[(ks * 64 + mt * 16 + prow + 8) * PLD + pcol];
                *(float2*)q1 = make_float2(aA[2] + aB[2] + aC[2], aA[3] + aB[3] + aC[3]);
            }
            __syncthreads();   // before next stage overwrites buf
        }

        // ---- gates ----
        float si = p0 + bias0, sf = p1 + bias1, so = p2 + bias2, sg = p3 + bias3;
#pragma unroll
        for (int s = 0; s < 4; s++) {
            const float* pr = &part[(s * 64 + b) * PLD];
            si += pr[jj];
            sf += pr[8 + jj];
            so += pr[16 + jj];
            sg += pr[24 + jj];
        }
        float ig = 1.0f / (1.0f + expf(-si));
        float fg = 1.0f / (1.0f + expf(-sf));
        float og = 1.0f / (1.0f + expf(-so));
        float gg = tanhf(sg);
        c_reg = fg * c_reg + ig * gg;
        float hn = og * tanhf(c_reg);

        int hidx = b * HID + j;
        if (t == SEQ - 1) g_h[hidx] = hn;
        __nv_bfloat16 hh = __float2bfloat16(hn);
        int wr = 1 - rd;
        g_hbufhi[wr][hidx] = hh;
        g_hbuflo[wr][hidx] = __float2bfloat16(hn - __bfloat162float(hh));

        // ---- grid barrier: distributed flags (no same-address contention) ----
        __threadfence();                 // own h writes visible gpu-wide
        __syncthreads();                 // all threads of CTA fenced
        if (tid == 0)
            *(volatile unsigned*)&g_flag[blockIdx.x * 32] = (unsigned)(t + 1);
        if (tid < NCTA) {
            while (*(volatile unsigned*)&g_flag[tid * 32] < (unsigned)(t + 1))
                __nanosleep(20);
        }
        __syncthreads();
        __threadfence();                 // acquire: drop stale lines
    }
}

// ---------------------------------------------------------------------------
// Final: out[b, o] = dot(h[b,:], w[o,:])
// ---------------------------------------------------------------------------
__global__ void k_final(const float* __restrict__ w, float* __restrict__ out) {
    int gw   = (blockIdx.x * blockDim.x + threadIdx.x) >> 5;
    int lane = threadIdx.x & 31;
    if (gw >= BAT * OUTD) return;
    int b = gw >> 9, o = gw & (OUTD - 1);
    const float* hr = g_h + b * HID;
    const float* wr = w + (size_t)o * HID;
    float s = 0.0f;
    for (int k = lane; k < HID; k += 32) s = fmaf(hr[k], wr[k], s);
#pragma unroll
    for (int off = 16; off > 0; off >>= 1) s += __shfl_down_sync(0xFFFFFFFFu, s, off);
    if (lane == 0) out[b * OUTD + o] = s;
}

// ---------------------------------------------------------------------------
// Launch (graph-capturable)
// ---------------------------------------------------------------------------
extern "C" void kernel_launch(void* const* d_in, const int* in_sizes, int n_in,
                              void* d_out, int out_size) {
    const float* X    = (const float*)d_in[0];
    const float* c0   = (const float*)d_in[1];
    const float* h0   = (const float*)d_in[2];
    const float* w_hi = (const float*)d_in[3];
    const float* w_xi = (const float*)d_in[4];
    const float* b_hi = (const float*)d_in[5];
    const float* b_xi = (const float*)d_in[6];
    const float* w_hf = (const float*)d_in[7];
    const float* w_xf = (const float*)d_in[8];
    const float* b_hf = (const float*)d_in[9];
    const float* b_xf = (const float*)d_in[10];
    const float* w_ho = (const float*)d_in[11];
    const float* w_xo = (const float*)d_in[12];
    const float* b_ho = (const float*)d_in[13];
    const float* b_xo = (const float*)d_in[14];
    const float* w_hg = (const float*)d_in[15];
    const float* w_xg = (const float*)d_in[16];
    const float* b_hg = (const float*)d_in[17];
    const float* b_xg = (const float*)d_in[18];
    const float* w    = (const float*)d_in[19];
    float* out = (float*)d_out;

    const int RNN_SMEM = 2 * 2 * 16 * ALD * 2 + 4 * 64 * PLD * 4;   // 166,912 B
    cudaFuncSetAttribute(k_rnn, cudaFuncAttributeMaxDynamicSharedMemorySize, RNN_SMEM);
    cudaFuncSetAttribute(k_xproj3, cudaFuncAttributeMaxDynamicSharedMemorySize, XP_SMEM);

    k_splitX<<<8192, 256>>>(X);
    k_splitWx<<<4096, 256>>>(w_xi, w_xf, w_xo, w_xg);
    k_splitWh<<<4096, 256>>>(w_hi, w_hf, w_ho, w_hg);
    k_init<<<(BAT * HID + 255) / 256, 256>>>(c0, h0, b_hi, b_xi, b_hf, b_xf,
                                             b_ho, b_xo, b_hg, b_xg);

    k_xproj3<<<dim3(NG / 64, (BAT * SEQ) / 128), 256, XP_SMEM>>>();

    k_rnn<<<NCTA, 512, RNN_SMEM>>>();

    k_final<<<(BAT * OUTD * 32 + 255) / 256, 256>>>(w, out);
}

// round 15
// speedup vs baseline: 5.5045x; 1.1492x over previous
#include <cuda_runtime.h>
#include <cuda_fp16.h>
#include <cstdint>

// Problem dims
#define HID 1024
#define INP 1024
#define OUTD 512
#define BAT 64
#define SEQ 512
#define NG  4096   // 4 gates * HID

#define NCTA 128   // persistent recurrence CTAs (1/SM, all co-resident)
#define ALD  1032  // rnn smem A row stride in halves (conflict-free ldmatrix)
#define PLD  34    // rnn partials row stride in floats

// ---------------------------------------------------------------------------
// Device scratch
// ---------------------------------------------------------------------------
__device__ __half g_XH[(size_t)BAT * SEQ * INP];      // X hi (fp16)
__device__ __half g_XL[(size_t)BAT * SEQ * INP];      // X lo (fp16)
__device__ __half g_WxH[(size_t)NG * INP];            // Wx single fp16
__device__ __half g_WhH[(size_t)NG * HID];            // Wh single fp16
__device__ float  g_P[(size_t)SEQ * BAT * NG];        // [t][b][4H]
__device__ float  g_bias[NG];
__device__ float  g_c[BAT * HID];
__device__ float  g_h[BAT * HID];
__device__ __half g_hbh[2][BAT * HID];                // h hi, double-buffered
__device__ __half g_hbl[2][BAT * HID];                // h lo
__device__ unsigned g_flag[NCTA * 32];                // barrier flags, 128B strided

// ---------------------------------------------------------------------------
// PTX helpers
// ---------------------------------------------------------------------------
__device__ __forceinline__ void mma16816h(float* d, const uint32_t* a, const uint32_t* b) {
    asm volatile(
        "mma.sync.aligned.m16n8k16.row.col.f32.f16.f16.f32 "
        "{%0,%1,%2,%3}, {%4,%5,%6,%7}, {%8,%9}, {%0,%1,%2,%3};"
        : "+f"(d[0]), "+f"(d[1]), "+f"(d[2]), "+f"(d[3])
        : "r"(a[0]), "r"(a[1]), "r"(a[2]), "r"(a[3]), "r"(b[0]), "r"(b[1]));
}
__device__ __forceinline__ void ldmatrix_x4(uint32_t* r, uint32_t addr) {
    asm volatile("ldmatrix.sync.aligned.m8n8.x4.shared.b16 {%0,%1,%2,%3}, [%4];"
                 : "=r"(r[0]), "=r"(r[1]), "=r"(r[2]), "=r"(r[3]) : "r"(addr));
}
__device__ __forceinline__ void cp_async16(uint32_t dst, const void* src) {
    asm volatile("cp.async.cg.shared.global [%0], [%1], 16;" :: "r"(dst), "l"(src) : "memory");
}
__device__ __forceinline__ void cp_commit() { asm volatile("cp.async.commit_group;"); }
template <int N>
__device__ __forceinline__ void cp_wait() { asm volatile("cp.async.wait_group %0;" :: "n"(N)); }

__device__ __forceinline__ float fast_sigmoid(float x) {
    return 1.0f / (1.0f + __expf(-x));
}
__device__ __forceinline__ float fast_tanh(float x) {
    return 1.0f - 2.0f / (__expf(2.0f * x) + 1.0f);
}

// ---------------------------------------------------------------------------
// Prep kernels: fp16 hi/lo split for activations, single fp16 for weights
// ---------------------------------------------------------------------------
__global__ void k_splitX(const float* __restrict__ X) {
    size_t n = (size_t)BAT * SEQ * INP;
    for (size_t i = (size_t)blockIdx.x * blockDim.x + threadIdx.x; i < n;
         i += (size_t)gridDim.x * blockDim.x) {
        float v = X[i];
        __half hv = __float2half_rn(v);
        g_XH[i] = hv;
        g_XL[i] = __float2half_rn(v - __half2float(hv));
    }
}

__global__ void k_cvtWx(const float* __restrict__ w0, const float* __restrict__ w1,
                        const float* __restrict__ w2, const float* __restrict__ w3) {
    const float* src[4] = {w0, w1, w2, w3};
    size_t n = (size_t)NG * INP;
    for (size_t i = (size_t)blockIdx.x * blockDim.x + threadIdx.x; i < n;
         i += (size_t)gridDim.x * blockDim.x) {
        int    g   = (int)(i >> 20);
        size_t rem = i & ((size_t)(1u << 20) - 1);
        g_WxH[i] = __float2half_rn(src[g][rem]);
    }
}

__global__ void k_cvtWh(const float* __restrict__ w0, const float* __restrict__ w1,
                        const float* __restrict__ w2, const float* __restrict__ w3) {
    const float* src[4] = {w0, w1, w2, w3};
    size_t n = (size_t)NG * HID;
    for (size_t i = (size_t)blockIdx.x * blockDim.x + threadIdx.x; i < n;
         i += (size_t)gridDim.x * blockDim.x) {
        int    g   = (int)(i >> 20);
        size_t rem = i & ((size_t)(1u << 20) - 1);
        g_WhH[i] = __float2half_rn(src[g][rem]);
    }
}

__global__ void k_init(const float* __restrict__ c0, const float* __restrict__ h0,
                       const float* __restrict__ bhi_, const float* __restrict__ bxi_,
                       const float* __restrict__ bhf_, const float* __restrict__ bxf_,
                       const float* __restrict__ bho_, const float* __restrict__ bxo_,
                       const float* __restrict__ bhg_, const float* __restrict__ bxg_) {
    int idx = blockIdx.x * blockDim.x + threadIdx.x;
    if (idx < NCTA * 32) g_flag[idx] = 0u;
    if (idx < BAT * HID) {
        int j = idx & (HID - 1);
        g_c[idx] = c0[j];
        float hv = h0[j];
        __half hh = __float2half_rn(hv);
        g_hbh[0][idx] = hh;
        g_hbl[0][idx] = __float2half_rn(hv - __half2float(hh));
    }
    if (idx < NG) {
        int g = idx >> 10, j = idx & (HID - 1);
        const float* bh[4] = {bhi_, bhf_, bho_, bhg_};
        const float* bx[4] = {bxi_, bxf_, bxo_, bxg_};
        g_bias[idx] = bh[g][j] + bx[g][j];
    }
}

// ---------------------------------------------------------------------------
// X projection: 2-term fp16 (Xhi + Xlo) @ WxH^T, mma.16816 + ldmatrix +
// cp.async double-buffered. CTA tile M=128 x N=64, warp tile 32x32.
// ---------------------------------------------------------------------------
#define XLD 72
#define XO_AH 0
#define XO_AL 18432
#define XO_BH 36864
#define XBUF  46080
#define XP_SMEM (2 * XBUF)   // 92,160 B

__global__ __launch_bounds__(256) void k_xproj() {
    extern __shared__ char smem[];
    const uint32_t sb = (uint32_t)__cvta_generic_to_shared(smem);

    const int tid   = threadIdx.x;
    const int wid   = tid >> 5;
    const int lane  = tid & 31;
    const int mwarp = wid & 3;
    const int nwarp = wid >> 2;
    const int n0    = blockIdx.x * 64;
    const int m0    = blockIdx.y * 128;

    float acc[2][4][4];
#pragma unroll
    for (int mt = 0; mt < 2; mt++)
#pragma unroll
        for (int nt = 0; nt < 4; nt++)
#pragma unroll
            for (int q = 0; q < 4; q++) acc[mt][nt][q] = 0.0f;

    const uint32_t a_off = (uint32_t)((lane & 15) * (XLD * 2) + (lane >> 4) * 16);
    const int bmat = lane >> 3;
    const int brow = lane & 7;
    const uint32_t b_off = (uint32_t)(((bmat >> 1) * 8 + brow) * (XLD * 2) + (bmat & 1) * 16);

    auto fill = [&](int k0, uint32_t bb) {
#pragma unroll
        for (int q = 0; q < 10; q++) {
            int idx = q * 256 + tid;          // 0..2559
            if (idx < 2048) {                 // A: hi then lo (128 rows x 8 units x 2)
                int half_ = idx >> 10, row = (idx >> 3) & 127, c = idx & 7;
                const __half* src =
                    (half_ ? g_XL : g_XH) + (size_t)(m0 + row) * INP + k0 + c * 8;
                cp_async16(bb + (half_ ? XO_AL : XO_AH) + (uint32_t)(row * XLD + c * 8) * 2, src);
            } else {                          // B: single (64 rows x 8 units)
                int r2 = idx - 2048;
                int row = (r2 >> 3) & 63, c = r2 & 7;
                const __half* src = g_WxH + (size_t)(n0 + row) * INP + k0 + c * 8;
                cp_async16(bb + XO_BH + (uint32_t)(row * XLD + c * 8) * 2, src);
            }
        }
        cp_commit();
    };

    fill(0, sb);
    for (int ch = 0; ch < 16; ch++) {
        const uint32_t bb = sb + (ch & 1) * XBUF;
        if (ch < 15) {
            fill((ch + 1) * 64, sb + ((ch + 1) & 1) * XBUF);
            cp_wait<1>();
        } else {
            cp_wait<0>();
        }
        __syncthreads();

#pragma unroll
        for (int kk = 0; kk < 4; kk++) {
            uint32_t ah[2][4], al[2][4];
#pragma unroll
            for (int mt = 0; mt < 2; mt++) {
                uint32_t base = (uint32_t)((mwarp * 32 + mt * 16) * (XLD * 2) + kk * 32);
                ldmatrix_x4(ah[mt], bb + XO_AH + base + a_off);
                ldmatrix_x4(al[mt], bb + XO_AL + base + a_off);
            }
            uint32_t bh[8];
#pragma unroll
            for (int g = 0; g < 2; g++) {
                uint32_t base = (uint32_t)((nwarp * 32 + g * 16) * (XLD * 2) + kk * 32);
                ldmatrix_x4(bh + g * 4, bb + XO_BH + base + b_off);
            }
#pragma unroll
            for (int mt = 0; mt < 2; mt++)
#pragma unroll
                for (int nt = 0; nt < 4; nt++) {
                    mma16816h(acc[mt][nt], ah[mt], bh + nt * 2);
                    mma16816h(acc[mt][nt], al[mt], bh + nt * 2);
                }
        }
        __syncthreads();
    }

    // Epilogue: g_P in [t][b][n] layout (m = b*SEQ + t)
#pragma unroll
    for (int mt = 0; mt < 2; mt++) {
        int mrow0 = m0 + mwarp * 32 + mt * 16 + (lane >> 2);
#pragma unroll
        for (int half_ = 0; half_ < 2; half_++) {
            int m = mrow0 + half_ * 8;
            int b = m >> 9, t = m & (SEQ - 1);
            float* dst = g_P + ((size_t)t * BAT + b) * NG + n0 + nwarp * 32 + (lane & 3) * 2;
#pragma unroll
            for (int nt = 0; nt < 4; nt++)
                *(float2*)(dst + nt * 8) =
                    make_float2(acc[mt][nt][half_ * 2], acc[mt][nt][half_ * 2 + 1]);
        }
    }
}

// ---------------------------------------------------------------------------
// Persistent recurrence: 2-term fp16, weights-in-registers (single fp16),
// warp map (ng:2 n-groups of 16) x (ks:8 K-sections of 128) to cut A-read
// redundancy 4x -> 2x on the smem crossbar. Distributed-flag grid barrier.
// ---------------------------------------------------------------------------
__global__ __launch_bounds__(512, 1) void k_rnn() {
    extern __shared__ char dynsm[];
    __half* Ah = (__half*)dynsm;                      // [2][16][ALD]
    __half* Al = Ah + 2 * 16 * ALD;                   // [2][16][ALD]
    float* part = (float*)(Al + 2 * 16 * ALD);        // [8][64][PLD]

    const int tid  = threadIdx.x;
    const int j0   = blockIdx.x * 8;
    const int wrp  = tid >> 5;
    const int lane = tid & 31;
    const int ng   = wrp >> 3;   // n-group: gates {2ng, 2ng+1}
    const int ks   = wrp & 7;    // K-section [ks*128, +128)

    const uint32_t Ah_u = (uint32_t)__cvta_generic_to_shared(Ah);
    const uint32_t Al_u = (uint32_t)__cvta_generic_to_shared(Al);

    // Warp-unique single-fp16 weight fragments in registers (loaded once).
    // bw[kk][tile][reg]: tile = n8 group; thread holds W[n][k..k+1], W[n][k+8..k+9]
    const int nlane = lane >> 2;
    const int klane = (lane & 3) * 2;
    uint32_t bw[8][2][2];
#pragma unroll
    for (int tt = 0; tt < 2; tt++) {
        const size_t wrow =
            (size_t)((ng * 2 + tt) * HID + j0 + nlane) * HID + ks * 128 + klane;
#pragma unroll
        for (int kk = 0; kk < 8; kk++) {
            bw[kk][tt][0] = *(const uint32_t*)&g_WhH[wrow + kk * 16];
            bw[kk][tt][1] = *(const uint32_t*)&g_WhH[wrow + kk * 16 + 8];
        }
    }

    const uint32_t a_lane_off = (uint32_t)((lane & 15) * ALD + (lane >> 4) * 8);

    const int b  = tid >> 3;
    const int jj = tid & 7;
    const int j  = j0 + jj;
    float c_reg = g_c[b * HID + j];
    const float bias0 = g_bias[j];
    const float bias1 = g_bias[HID + j];
    const float bias2 = g_bias[2 * HID + j];
    const float bias3 = g_bias[3 * HID + j];

    __syncthreads();

    for (int t = 0; t < SEQ; t++) {
        const int rd = t & 1;
        const __half* hbh = g_hbh[rd];
        const __half* hbl = g_hbl[rd];

        size_t pb = ((size_t)t * BAT + b) * NG + j;
        float p0 = g_P[pb];
        float p1 = g_P[pb + HID];
        float p2 = g_P[pb + 2 * HID];
        float p3 = g_P[pb + 3 * HID];

        // ---- stage chunk 0 (16 batch rows, full K, hi+lo) ----
        {
#pragma unroll
            for (int q = 0; q < 8; q++) {
                int idx = q * 512 + tid;
                int half_ = idx >> 11, rr = (idx >> 7) & 15, c = idx & 127;
                const __half* src = (half_ ? hbl : hbh) + (size_t)rr * HID + c * 8;
                uint32_t dst = (half_ ? Al_u : Ah_u) + (uint32_t)(rr * ALD + c * 8) * 2;
                cp_async16(dst, src);
            }
            cp_commit();
        }

        const int prow = lane >> 2;
        const int pc0  = ng * 16 + (lane & 3) * 2;

        for (int mt = 0; mt < 4; mt++) {
            const int buf = mt & 1;
            if (mt < 3) {
                const int nb = 1 - buf;
#pragma unroll
                for (int q = 0; q < 8; q++) {
                    int idx = q * 512 + tid;
                    int half_ = idx >> 11, rr = (idx >> 7) & 15, c = idx & 127;
                    const __half* src =
                        (half_ ? hbl : hbh) + (size_t)((mt + 1) * 16 + rr) * HID + c * 8;
                    uint32_t dst = (half_ ? Al_u : Ah_u) +
                                   (uint32_t)((nb * 16 + rr) * ALD + c * 8) * 2;
                    cp_async16(dst, src);
                }
                cp_commit();
                cp_wait<1>();
            } else {
                cp_wait<0>();
            }
            __syncthreads();

            // 2-term fp16: acc = Ahi*W + Alo*W   (two n8 tiles = the 2 gates)
            float a0[4] = {0.f, 0.f, 0.f, 0.f};
            float a1[4] = {0.f, 0.f, 0.f, 0.f};
            const uint32_t ahb = Ah_u + (uint32_t)(buf * 16 * ALD + a_lane_off + ks * 128) * 2;
            const uint32_t alb = Al_u + (uint32_t)(buf * 16 * ALD + a_lane_off + ks * 128) * 2;
#pragma unroll
            for (int kk = 0; kk < 8; kk++) {
                uint32_t ah[4], al[4];
                ldmatrix_x4(ah, ahb + kk * 32);
                ldmatrix_x4(al, alb + kk * 32);
                mma16816h(a0, ah, bw[kk][0]);
                mma16816h(a0, al, bw[kk][0]);
                mma16816h(a1, ah, bw[kk][1]);
                mma16816h(a1, al, bw[kk][1]);
            }
            // partials: part[ks][mt*16 + row][ng*16 + tt*8 + col]
            {
                float* q0 = &part[(ks * 64 + mt * 16 + prow) * PLD + pc0];
                *(float2*)q0 = make_float2(a0[0], a0[1]);
                *(float2*)(q0 + 8) = make_float2(a1[0], a1[1]);
                float* q1 = &part[(ks * 64 + mt * 16 + prow + 8) * PLD + pc0];
                *(float2*)q1 = make_float2(a0[2], a0[3]);
                *(float2*)(q1 + 8) = make_float2(a1[2], a1[3]);
            }
            __syncthreads();
        }

        // ---- gates: sum 8 K-section partials + P + bias ----
        float si = p0 + bias0, sf = p1 + bias1, so = p2 + bias2, sg = p3 + bias3;
#pragma unroll
        for (int s = 0; s < 8; s++) {
            const float* pr = &part[(s * 64 + b) * PLD];
            si += pr[jj];
            sf += pr[8 + jj];
            so += pr[16 + jj];
            sg += pr[24 + jj];
        }
        float ig = fast_sigmoid(si);
        float fg = fast_sigmoid(sf);
        float og = fast_sigmoid(so);
        float gg = fast_tanh(sg);
        c_reg = fg * c_reg + ig * gg;
        float hn = og * fast_tanh(c_reg);

        int hidx = b * HID + j;
        if (t == SEQ - 1) g_h[hidx] = hn;
        __half hh = __float2half_rn(hn);
        int wr = 1 - rd;
        g_hbh[wr][hidx] = hh;
        g_hbl[wr][hidx] = __float2half_rn(hn - __half2float(hh));

        // ---- grid barrier: distributed flags ----
        __threadfence();
        __syncthreads();
        if (tid == 0)
            *(volatile unsigned*)&g_flag[blockIdx.x * 32] = (unsigned)(t + 1);
        if (tid < NCTA) {
            while (*(volatile unsigned*)&g_flag[tid * 32] < (unsigned)(t + 1))
                __nanosleep(20);
        }
        __syncthreads();
        __threadfence();
    }
}

// ---------------------------------------------------------------------------
// Final: out[b, o] = dot(h[b,:], w[o,:])
// ---------------------------------------------------------------------------
__global__ void k_final(const float* __restrict__ w, float* __restrict__ out) {
    int gw   = (blockIdx.x * blockDim.x + threadIdx.x) >> 5;
    int lane = threadIdx.x & 31;
    if (gw >= BAT * OUTD) return;
    int b = gw >> 9, o = gw & (OUTD - 1);
    const float* hr = g_h + b * HID;
    const float* wr = w + (size_t)o * HID;
    float s = 0.0f;
    for (int k = lane; k < HID; k += 32) s = fmaf(hr[k], wr[k], s);
#pragma unroll
    for (int off = 16; off > 0; off >>= 1) s += __shfl_down_sync(0xFFFFFFFFu, s, off);
    if (lane == 0) out[b * OUTD + o] = s;
}

// ---------------------------------------------------------------------------
// Launch (graph-capturable)
// ---------------------------------------------------------------------------
extern "C" void kernel_launch(void* const* d_in, const int* in_sizes, int n_in,
                              void* d_out, int out_size) {
    const float* X    = (const float*)d_in[0];
    const float* c0   = (const float*)d_in[1];
    const float* h0   = (const float*)d_in[2];
    const float* w_hi = (const float*)d_in[3];
    const float* w_xi = (const float*)d_in[4];
    const float* b_hi = (const float*)d_in[5];
    const float* b_xi = (const float*)d_in[6];
    const float* w_hf = (const float*)d_in[7];
    const float* w_xf = (const float*)d_in[8];
    const float* b_hf = (const float*)d_in[9];
    const float* b_xf = (const float*)d_in[10];
    const float* w_ho = (const float*)d_in[11];
    const float* w_xo = (const float*)d_in[12];
    const float* b_ho = (const float*)d_in[13];
    const float* b_xo = (const float*)d_in[14];
    const float* w_hg = (const float*)d_in[15];
    const float* w_xg = (const float*)d_in[16];
    const float* b_hg = (const float*)d_in[17];
    const float* b_xg = (const float*)d_in[18];
    const float* w    = (const float*)d_in[19];
    float* out = (float*)d_out;

    const int RNN_SMEM = 2 * 2 * 16 * ALD * 2 + 8 * 64 * PLD * 4;   // 201,728 B
    cudaFuncSetAttribute(k_rnn, cudaFuncAttributeMaxDynamicSharedMemorySize, RNN_SMEM);
    cudaFuncSetAttribute(k_xproj, cudaFuncAttributeMaxDynamicSharedMemorySize, XP_SMEM);

    k_splitX<<<8192, 256>>>(X);
    k_cvtWx<<<4096, 256>>>(w_xi, w_xf, w_xo, w_xg);
    k_cvtWh<<<4096, 256>>>(w_hi, w_hf, w_ho, w_hg);
    k_init<<<(BAT * HID + 255) / 256, 256>>>(c0, h0, b_hi, b_xi, b_hf, b_xf,
                                             b_ho, b_xo, b_hg, b_xg);

    k_xproj<<<dim3(NG / 64, (BAT * SEQ) / 128), 256, XP_SMEM>>>();

    k_rnn<<<NCTA, 512, RNN_SMEM>>>();

    k_final<<<(BAT * OUTD * 32 + 255) / 256, 256>>>(w, out);
}

// round 17
// speedup vs baseline: 6.8517x; 1.2448x over previous
#include <cuda_runtime.h>
#include <cuda_fp16.h>
#include <cstdint>

// Problem dims
#define HID 1024
#define INP 1024
#define OUTD 512
#define BAT 64
#define SEQ 512
#define NG  4096   // 4 gates * HID

#define NCTA 128   // persistent recurrence CTAs (1/SM, all co-resident)
#define ALD  1032  // rnn smem A row stride in halves (conflict-free ldmatrix)
#define PLD  34    // rnn partials row stride in floats

// ---------------------------------------------------------------------------
// Device scratch
// ---------------------------------------------------------------------------
__device__ __half g_XH[(size_t)BAT * SEQ * INP];      // X hi (fp16)
__device__ __half g_XL[(size_t)BAT * SEQ * INP];      // X lo (fp16)
__device__ __half g_WxH[(size_t)NG * INP];            // Wx single fp16
__device__ __half g_WhH[(size_t)NG * HID];            // Wh single fp16
__device__ float  g_P[(size_t)SEQ * BAT * NG];        // [t][b][4H]
__device__ float  g_bias[NG];
__device__ float  g_c[BAT * HID];
__device__ float  g_h[BAT * HID];
__device__ __half g_hb[2][BAT * HID];                 // h (fp16), double-buffered
__device__ unsigned g_flag[NCTA * 32];                // barrier flags, 128B strided

// ---------------------------------------------------------------------------
// PTX helpers
// ---------------------------------------------------------------------------
__device__ __forceinline__ void mma16816h(float* d, const uint32_t* a, const uint32_t* b) {
    asm volatile(
        "mma.sync.aligned.m16n8k16.row.col.f32.f16.f16.f32 "
        "{%0,%1,%2,%3}, {%4,%5,%6,%7}, {%8,%9}, {%0,%1,%2,%3};"
        : "+f"(d[0]), "+f"(d[1]), "+f"(d[2]), "+f"(d[3])
        : "r"(a[0]), "r"(a[1]), "r"(a[2]), "r"(a[3]), "r"(b[0]), "r"(b[1]));
}
__device__ __forceinline__ void ldmatrix_x4(uint32_t* r, uint32_t addr) {
    asm volatile("ldmatrix.sync.aligned.m8n8.x4.shared.b16 {%0,%1,%2,%3}, [%4];"
                 : "=r"(r[0]), "=r"(r[1]), "=r"(r[2]), "=r"(r[3]) : "r"(addr));
}
__device__ __forceinline__ void cp_async16(uint32_t dst, const void* src) {
    asm volatile("cp.async.cg.shared.global [%0], [%1], 16;" :: "r"(dst), "l"(src) : "memory");
}
__device__ __forceinline__ void cp_commit() { asm volatile("cp.async.commit_group;"); }
template <int N>
__device__ __forceinline__ void cp_wait() { asm volatile("cp.async.wait_group %0;" :: "n"(N)); }

__device__ __forceinline__ float fast_sigmoid(float x) {
    return 1.0f / (1.0f + __expf(-x));
}
__device__ __forceinline__ float fast_tanh(float x) {
    return 1.0f - 2.0f / (__expf(2.0f * x) + 1.0f);
}

// ---------------------------------------------------------------------------
// Prep kernels
// ---------------------------------------------------------------------------
__global__ void k_splitX(const float* __restrict__ X) {
    size_t n = (size_t)BAT * SEQ * INP;
    for (size_t i = (size_t)blockIdx.x * blockDim.x + threadIdx.x; i < n;
         i += (size_t)gridDim.x * blockDim.x) {
        float v = X[i];
        __half hv = __float2half_rn(v);
        g_XH[i] = hv;
        g_XL[i] = __float2half_rn(v - __half2float(hv));
    }
}

__global__ void k_cvtWx(const float* __restrict__ w0, const float* __restrict__ w1,
                        const float* __restrict__ w2, const float* __restrict__ w3) {
    const float* src[4] = {w0, w1, w2, w3};
    size_t n = (size_t)NG * INP;
    for (size_t i = (size_t)blockIdx.x * blockDim.x + threadIdx.x; i < n;
         i += (size_t)gridDim.x * blockDim.x) {
        int    g   = (int)(i >> 20);
        size_t rem = i & ((size_t)(1u << 20) - 1);
        g_WxH[i] = __float2half_rn(src[g][rem]);
    }
}

__global__ void k_cvtWh(const float* __restrict__ w0, const float* __restrict__ w1,
                        const float* __restrict__ w2, const float* __restrict__ w3) {
    const float* src[4] = {w0, w1, w2, w3};
    size_t n = (size_t)NG * HID;
    for (size_t i = (size_t)blockIdx.x * blockDim.x + threadIdx.x; i < n;
         i += (size_t)gridDim.x * blockDim.x) {
        int    g   = (int)(i >> 20);
        size_t rem = i & ((size_t)(1u << 20) - 1);
        g_WhH[i] = __float2half_rn(src[g][rem]);
    }
}

__global__ void k_init(const float* __restrict__ c0, const float* __restrict__ h0,
                       const float* __restrict__ bhi_, const float* __restrict__ bxi_,
                       const float* __restrict__ bhf_, const float* __restrict__ bxf_,
                       const float* __restrict__ bho_, const float* __restrict__ bxo_,
                       const float* __restrict__ bhg_, const float* __restrict__ bxg_) {
    int idx = blockIdx.x * blockDim.x + threadIdx.x;
    if (idx < NCTA * 32) g_flag[idx] = 0u;
    if (idx < BAT * HID) {
        int j = idx & (HID - 1);
        g_c[idx] = c0[j];
        g_hb[0][idx] = __float2half_rn(h0[j]);
    }
    if (idx < NG) {
        int g = idx >> 10, j = idx & (HID - 1);
        const float* bh[4] = {bhi_, bhf_, bho_, bhg_};
        const float* bx[4] = {bxi_, bxf_, bxo_, bxg_};
        g_bias[idx] = bh[g][j] + bx[g][j];
    }
}

// ---------------------------------------------------------------------------
// X projection: 2-term fp16 (Xhi + Xlo) @ WxH^T
// CTA tile M=128 x N=64, warp tile 32x32, cp.async double-buffered.
// ---------------------------------------------------------------------------
#define XLD 72
#define XO_AH 0
#define XO_AL 18432
#define XO_BH 36864
#define XBUF  46080
#define XP_SMEM (2 * XBUF)   // 92,160 B

__global__ __launch_bounds__(256) void k_xproj() {
    extern __shared__ char smem[];
    const uint32_t sb = (uint32_t)__cvta_generic_to_shared(smem);

    const int tid   = threadIdx.x;
    const int wid   = tid >> 5;
    const int lane  = tid & 31;
    const int mwarp = wid & 3;
    const int nwarp = wid >> 2;
    const int n0    = blockIdx.x * 64;
    const int m0    = blockIdx.y * 128;

    float acc[2][4][4];
#pragma unroll
    for (int mt = 0; mt < 2; mt++)
#pragma unroll
        for (int nt = 0; nt < 4; nt++)
#pragma unroll
            for (int q = 0; q < 4; q++) acc[mt][nt][q] = 0.0f;

    const uint32_t a_off = (uint32_t)((lane & 15) * (XLD * 2) + (lane >> 4) * 16);
    const int bmat = lane >> 3;
    const int brow = lane & 7;
    const uint32_t b_off = (uint32_t)(((bmat >> 1) * 8 + brow) * (XLD * 2) + (bmat & 1) * 16);

    auto fill = [&](int k0, uint32_t bb) {
#pragma unroll
        for (int q = 0; q < 10; q++) {
            int idx = q * 256 + tid;
            if (idx < 2048) {
                int half_ = idx >> 10, row = (idx >> 3) & 127, c = idx & 7;
                const __half* src =
                    (half_ ? g_XL : g_XH) + (size_t)(m0 + row) * INP + k0 + c * 8;
                cp_async16(bb + (half_ ? XO_AL : XO_AH) + (uint32_t)(row * XLD + c * 8) * 2, src);
            } else {
                int r2 = idx - 2048;
                int row = (r2 >> 3) & 63, c = r2 & 7;
                const __half* src = g_WxH + (size_t)(n0 + row) * INP + k0 + c * 8;
                cp_async16(bb + XO_BH + (uint32_t)(row * XLD + c * 8) * 2, src);
            }
        }
        cp_commit();
    };

    fill(0, sb);
    for (int ch = 0; ch < 16; ch++) {
        const uint32_t bb = sb + (ch & 1) * XBUF;
        if (ch < 15) {
            fill((ch + 1) * 64, sb + ((ch + 1) & 1) * XBUF);
            cp_wait<1>();
        } else {
            cp_wait<0>();
        }
        __syncthreads();

#pragma unroll
        for (int kk = 0; kk < 4; kk++) {
            uint32_t ah[2][4], al[2][4];
#pragma unroll
            for (int mt = 0; mt < 2; mt++) {
                uint32_t base = (uint32_t)((mwarp * 32 + mt * 16) * (XLD * 2) + kk * 32);
                ldmatrix_x4(ah[mt], bb + XO_AH + base + a_off);
                ldmatrix_x4(al[mt], bb + XO_AL + base + a_off);
            }
            uint32_t bh[8];
#pragma unroll
            for (int g = 0; g < 2; g++) {
                uint32_t base = (uint32_t)((nwarp * 32 + g * 16) * (XLD * 2) + kk * 32);
                ldmatrix_x4(bh + g * 4, bb + XO_BH + base + b_off);
            }
#pragma unroll
            for (int mt = 0; mt < 2; mt++)
#pragma unroll
                for (int nt = 0; nt < 4; nt++) {
                    mma16816h(acc[mt][nt], ah[mt], bh + nt * 2);
                    mma16816h(acc[mt][nt], al[mt], bh + nt * 2);
                }
        }
        __syncthreads();
    }

#pragma unroll
    for (int mt = 0; mt < 2; mt++) {
        int mrow0 = m0 + mwarp * 32 + mt * 16 + (lane >> 2);
#pragma unroll
        for (int half_ = 0; half_ < 2; half_++) {
            int m = mrow0 + half_ * 8;
            int b = m >> 9, t = m & (SEQ - 1);
            float* dst = g_P + ((size_t)t * BAT + b) * NG + n0 + nwarp * 32 + (lane & 3) * 2;
#pragma unroll
            for (int nt = 0; nt < 4; nt++)
                *(float2*)(dst + nt * 8) =
                    make_float2(acc[mt][nt][half_ * 2], acc[mt][nt][half_ * 2 + 1]);
        }
    }
}

// ---------------------------------------------------------------------------
// Persistent recurrence: single-fp16 h, fp16 weights-in-registers.
// CTA: hidden cols [j0,j0+8) x 4 gates (N=32), M=64, K=1024.
// 16 warps = (ng:2 n-groups of 2 gates) x (ks:8 K-sections of 128).
// h staged in two 32-row chunks (both cp.async issued up-front, double buffer).
// ---------------------------------------------------------------------------
__global__ __launch_bounds__(512, 1) void k_rnn() {
    extern __shared__ char dynsm[];
    __half* Ah = (__half*)dynsm;                      // [2][32][ALD]
    float* part = (float*)(Ah + 2 * 32 * ALD);        // [8][64][PLD]

    const int tid  = threadIdx.x;
    const int j0   = blockIdx.x * 8;
    const int wrp  = tid >> 5;
    const int lane = tid & 31;
    const int ng   = wrp >> 3;   // n-group: gates {2ng, 2ng+1}
    const int ks   = wrp & 7;    // K-section [ks*128, +128)

    const uint32_t Ah_u = (uint32_t)__cvta_generic_to_shared(Ah);

    // Warp-unique fp16 weight fragments in registers (loaded once)
    const int nlane = lane >> 2;
    const int klane = (lane & 3) * 2;
    uint32_t bw[8][2][2];
#pragma unroll
    for (int tt = 0; tt < 2; tt++) {
        const size_t wrow =
            (size_t)((ng * 2 + tt) * HID + j0 + nlane) * HID + ks * 128 + klane;
#pragma unroll
        for (int kk = 0; kk < 8; kk++) {
            bw[kk][tt][0] = *(const uint32_t*)&g_WhH[wrow + kk * 16];
            bw[kk][tt][1] = *(const uint32_t*)&g_WhH[wrow + kk * 16 + 8];
        }
    }

    const uint32_t a_lane_off = (uint32_t)((lane & 15) * ALD + (lane >> 4) * 8);

    const int b  = tid >> 3;
    const int jj = tid & 7;
    const int j  = j0 + jj;
    float c_reg = g_c[b * HID + j];
    const float bias0 = g_bias[j];
    const float bias1 = g_bias[HID + j];
    const float bias2 = g_bias[2 * HID + j];
    const float bias3 = g_bias[3 * HID + j];

    const int prow = lane >> 2;
    const int pc0  = ng * 16 + (lane & 3) * 2;

    __syncthreads();

    for (int t = 0; t < SEQ; t++) {
        const int rd = t & 1;
        const __half* hb = g_hb[rd];

        // Prefetch this thread's x-projection values (DRAM, overlaps staging)
        size_t pb = ((size_t)t * BAT + b) * NG + j;
        float p0 = g_P[pb];
        float p1 = g_P[pb + HID];
        float p2 = g_P[pb + 2 * HID];
        float p3 = g_P[pb + 3 * HID];

        // ---- stage BOTH 32-row chunks up-front (max MLP on L2 reads) ----
#pragma unroll
        for (int q = 0; q < 8; q++) {              // chunk 0: rows 0..31
            int idx = q * 512 + tid;
            int rr = idx >> 7, c = idx & 127;
            cp_async16(Ah_u + (uint32_t)(rr * ALD + c * 8) * 2,
                       hb + (size_t)rr * HID + c * 8);
        }
        cp_commit();
#pragma unroll
        for (int q = 0; q < 8; q++) {              // chunk 1: rows 32..63
            int idx = q * 512 + tid;
            int rr = idx >> 7, c = idx & 127;
            cp_async16(Ah_u + (uint32_t)((32 + rr) * ALD + c * 8) * 2,
                       hb + (size_t)(32 + rr) * HID + c * 8);
        }
        cp_commit();

#pragma unroll
        for (int ch = 0; ch < 2; ch++) {
            if (ch == 0) cp_wait<1>(); else cp_wait<0>();
            __syncthreads();

#pragma unroll
            for (int sub = 0; sub < 2; sub++) {    // two 16-row m-tiles per chunk
                float a0[4] = {0.f, 0.f, 0.f, 0.f};
                float a1[4] = {0.f, 0.f, 0.f, 0.f};
                const uint32_t ab =
                    Ah_u + (uint32_t)((ch * 32 + sub * 16) * ALD + a_lane_off + ks * 128) * 2;
#pragma unroll
                for (int kk = 0; kk < 8; kk++) {
                    uint32_t ah[4];
                    ldmatrix_x4(ah, ab + kk * 32);
                    mma16816h(a0, ah, bw[kk][0]);
                    mma16816h(a1, ah, bw[kk][1]);
                }
                const int mrow = ch * 32 + sub * 16;
                float* q0 = &part[(ks * 64 + mrow + prow) * PLD + pc0];
                *(float2*)q0 = make_float2(a0[0], a0[1]);
                *(float2*)(q0 + 8) = make_float2(a1[0], a1[1]);
                float* q1 = &part[(ks * 64 + mrow + prow + 8) * PLD + pc0];
                *(float2*)q1 = make_float2(a0[2], a0[3]);
                *(float2*)(q1 + 8) = make_float2(a1[2], a1[3]);
            }
        }
        __syncthreads();

        // ---- gates: sum 8 K-section partials + P + bias ----
        float si = p0 + bias0, sf = p1 + bias1, so = p2 + bias2, sg = p3 + bias3;
#pragma unroll
        for (int s = 0; s < 8; s++) {
            const float* pr = &part[(s * 64 + b) * PLD];
            si += pr[jj];
            sf += pr[8 + jj];
            so += pr[16 + jj];
            sg += pr[24 + jj];
        }
        float ig = fast_sigmoid(si);
        float fg = fast_sigmoid(sf);
        float og = fast_sigmoid(so);
        float gg = fast_tanh(sg);
        c_reg = fg * c_reg + ig * gg;
        float hn = og * fast_tanh(c_reg);

        int hidx = b * HID + j;
        if (t == SEQ - 1) g_h[hidx] = hn;
        g_hb[1 - rd][hidx] = __float2half_rn(hn);

        // ---- grid barrier: distributed flags ----
        __threadfence();
        __syncthreads();
        if (tid == 0)
            *(volatile unsigned*)&g_flag[blockIdx.x * 32] = (unsigned)(t + 1);
        if (tid < NCTA) {
            while (*(volatile unsigned*)&g_flag[tid * 32] < (unsigned)(t + 1))
                __nanosleep(20);
        }
        __syncthreads();
        __threadfence();
    }
}

// ---------------------------------------------------------------------------
// Final: out[b, o] = dot(h[b,:], w[o,:])
// ---------------------------------------------------------------------------
__global__ void k_final(const float* __restrict__ w, float* __restrict__ out) {
    int gw   = (blockIdx.x * blockDim.x + threadIdx.x) >> 5;
    int lane = threadIdx.x & 31;
    if (gw >= BAT * OUTD) return;
    int b = gw >> 9, o = gw & (OUTD - 1);
    const float* hr = g_h + b * HID;
    const float* wr = w + (size_t)o * HID;
    float s = 0.0f;
    for (int k = lane; k < HID; k += 32) s = fmaf(hr[k], wr[k], s);
#pragma unroll
    for (int off = 16; off > 0; off >>= 1) s += __shfl_down_sync(0xFFFFFFFFu, s, off);
    if (lane == 0) out[b * OUTD + o] = s;
}

// ---------------------------------------------------------------------------
// Launch (graph-capturable)
// ---------------------------------------------------------------------------
extern "C" void kernel_launch(void* const* d_in, const int* in_sizes, int n_in,
                              void* d_out, int out_size) {
    const float* X    = (const float*)d_in[0];
    const float* c0   = (const float*)d_in[1];
    const float* h0   = (const float*)d_in[2];
    const float* w_hi = (const float*)d_in[3];
    const float* w_xi = (const float*)d_in[4];
    const float* b_hi = (const float*)d_in[5];
    const float* b_xi = (const float*)d_in[6];
    const float* w_hf = (const float*)d_in[7];
    const float* w_xf = (const float*)d_in[8];
    const float* b_hf = (const float*)d_in[9];
    const float* b_xf = (const float*)d_in[10];
    const float* w_ho = (const float*)d_in[11];
    const float* w_xo = (const float*)d_in[12];
    const float* b_ho = (const float*)d_in[13];
    const float* b_xo = (const float*)d_in[14];
    const float* w_hg = (const float*)d_in[15];
    const float* w_xg = (const float*)d_in[16];
    const float* b_hg = (const float*)d_in[17];
    const float* b_xg = (const float*)d_in[18];
    const float* w    = (const float*)d_in[19];
    float* out = (float*)d_out;

    const int RNN_SMEM = 2 * 32 * ALD * 2 + 8 * 64 * PLD * 4;   // 201,728 B
    cudaFuncSetAttribute(k_rnn, cudaFuncAttributeMaxDynamicSharedMemorySize, RNN_SMEM);
    cudaFuncSetAttribute(k_xproj, cudaFuncAttributeMaxDynamicSharedMemorySize, XP_SMEM);

    k_splitX<<<8192, 256>>>(X);
    k_cvtWx<<<4096, 256>>>(w_xi, w_xf, w_xo, w_xg);
    k_cvtWh<<<4096, 256>>>(w_hi, w_hf, w_ho, w_hg);
    k_init<<<(BAT * HID + 255) / 256, 256>>>(c0, h0, b_hi, b_xi, b_hf, b_xf,
                                             b_ho, b_xo, b_hg, b_xg);

    k_xproj<<<dim3(NG / 64, (BAT * SEQ) / 128), 256, XP_SMEM>>>();

    k_rnn<<<NCTA, 512, RNN_SMEM>>>();

    k_final<<<(BAT * OUTD * 32 + 255) / 256, 256>>>(w, out);
}